// round 1
// baseline (speedup 1.0000x reference)
#include <cuda_runtime.h>
#include <math.h>

#define SEQ 4096
#define DIM 2048
#define NH 16
#define DH 128

// Scratch (static device arrays — no allocations allowed)
__device__ float g_q[SEQ * DIM];
__device__ float g_k[SEQ * DIM];
__device__ float g_v[SEQ * DIM];
__device__ float g_att[SEQ * DIM];

// ---------------------------------------------------------------------------
// GEMM: C[M=4096, N=2048] = A[M, K=2048] @ W[K, N] + bias[N]
// Block tile 128x128, K-tile 8, 256 threads, 8x8 micro-tile per thread.
// ---------------------------------------------------------------------------
#define GBM 128
#define GBN 128
#define GBK 8

__global__ __launch_bounds__(256)
void gemm_bias_kernel(const float* __restrict__ A, const float* __restrict__ W,
                      const float* __restrict__ bias, float* __restrict__ C) {
    __shared__ float As[GBK][GBM + 4];   // transposed A tile, padded
    __shared__ float Bs[GBK][GBN];

    const int tid = threadIdx.x;
    const int tx = tid & 15;        // 16 col-threads
    const int ty = tid >> 4;        // 16 row-threads
    const int rowBase = blockIdx.y * GBM;
    const int colBase = blockIdx.x * GBN;

    float acc[8][8];
#pragma unroll
    for (int i = 0; i < 8; i++)
#pragma unroll
        for (int j = 0; j < 8; j++) acc[i][j] = 0.f;

    const float* Aptr = A + (size_t)rowBase * DIM;
    const float* Wptr = W + colBase;

    for (int k0 = 0; k0 < DIM; k0 += GBK) {
        // load A tile 128x8 (transposed into As[k][m])
#pragma unroll
        for (int i = 0; i < 4; i++) {
            int e = tid + i * 256;
            int r = e >> 3, c = e & 7;
            As[c][r] = Aptr[(size_t)r * DIM + k0 + c];
        }
        // load B tile 8x128
#pragma unroll
        for (int i = 0; i < 4; i++) {
            int e = tid + i * 256;
            int r = e >> 7, c = e & 127;
            Bs[r][c] = Wptr[(size_t)(k0 + r) * DIM + c];
        }
        __syncthreads();

#pragma unroll
        for (int kk = 0; kk < GBK; kk++) {
            float a[8], b[8];
#pragma unroll
            for (int i = 0; i < 8; i++) a[i] = As[kk][ty * 8 + i];
#pragma unroll
            for (int j = 0; j < 8; j++) b[j] = Bs[kk][tx + j * 16];
#pragma unroll
            for (int i = 0; i < 8; i++)
#pragma unroll
                for (int j = 0; j < 8; j++)
                    acc[i][j] += a[i] * b[j];
        }
        __syncthreads();
    }

#pragma unroll
    for (int i = 0; i < 8; i++) {
        int r = rowBase + ty * 8 + i;
#pragma unroll
        for (int j = 0; j < 8; j++) {
            int c = colBase + tx + j * 16;
            C[(size_t)r * DIM + c] = acc[i][j] + bias[c];
        }
    }
}

// ---------------------------------------------------------------------------
// RMSNorm (over full DIM=2048, before head split) + RoPE (interleaved pairs)
// One block per sequence position; handles both q and k rows in place.
// ---------------------------------------------------------------------------
__global__ __launch_bounds__(256)
void rmsnorm_rope_kernel(const float* __restrict__ fc, const float* __restrict__ fs,
                         const float* __restrict__ gq, const float* __restrict__ gk) {
    const int s = blockIdx.x;
    const int tid = threadIdx.x;
    float* qrow = g_q + (size_t)s * DIM;
    float* krow = g_k + (size_t)s * DIM;

    float q1[4], q2[4], k1[4], k2[4];
    float sq = 0.f, sk = 0.f;
#pragma unroll
    for (int j = 0; j < 4; j++) {
        int p = tid + j * 256;          // pair index 0..1023
        int h = p >> 6, jj = p & 63;
        int i1 = h * DH + 2 * jj;
        float2 qv = *(const float2*)(qrow + i1);
        float2 kv = *(const float2*)(krow + i1);
        q1[j] = qv.x; q2[j] = qv.y; k1[j] = kv.x; k2[j] = kv.y;
        sq += qv.x * qv.x + qv.y * qv.y;
        sk += kv.x * kv.x + kv.y * kv.y;
    }
#pragma unroll
    for (int off = 16; off > 0; off >>= 1) {
        sq += __shfl_xor_sync(0xffffffffu, sq, off);
        sk += __shfl_xor_sync(0xffffffffu, sk, off);
    }
    __shared__ float sh[16];
    if ((tid & 31) == 0) { sh[tid >> 5] = sq; sh[8 + (tid >> 5)] = sk; }
    __syncthreads();
    float tq = 0.f, tk = 0.f;
#pragma unroll
    for (int w = 0; w < 8; w++) { tq += sh[w]; tk += sh[8 + w]; }
    const float rq = rsqrtf(tq * (1.0f / DIM) + 1e-5f);
    const float rk = rsqrtf(tk * (1.0f / DIM) + 1e-5f);

#pragma unroll
    for (int j = 0; j < 4; j++) {
        int p = tid + j * 256;
        int h = p >> 6, jj = p & 63;
        int i1 = h * DH + 2 * jj;
        float c = fc[(size_t)s * DH + 2 * jj];        // cos from even slots
        float sn = fs[(size_t)s * DH + 2 * jj + 1];   // sin from odd slots
        float x1 = q1[j] * rq * gq[i1];
        float x2 = q2[j] * rq * gq[i1 + 1];
        float2 oq; oq.x = x1 * c - x2 * sn; oq.y = x1 * sn + x2 * c;
        *(float2*)(qrow + i1) = oq;
        x1 = k1[j] * rk * gk[i1];
        x2 = k2[j] * rk * gk[i1 + 1];
        float2 ok; ok.x = x1 * c - x2 * sn; ok.y = x1 * sn + x2 * c;
        *(float2*)(krow + i1) = ok;
    }
}

// ---------------------------------------------------------------------------
// Flash attention (fp32, online softmax). One block per (head, 64-query tile).
// ---------------------------------------------------------------------------
#define BQ 64
#define BKV 64
#define QSTR 129   // odd stride -> conflict-free lane-strided reads
#define KSTR 129
#define VSTR 128
#define PSTR 80    // 64+16: the two ty-groups per warp hit disjoint bank sets
#define ATTN_SMEM ((BQ * QSTR + BKV * KSTR + BKV * VSTR + BQ * PSTR) * 4)

__global__ __launch_bounds__(256)
void attn_kernel() {
    extern __shared__ float sm[];
    float* Qs = sm;
    float* Ks = Qs + BQ * QSTR;
    float* Vs = Ks + BKV * KSTR;
    float* Ps = Vs + BKV * VSTR;

    const int h = blockIdx.y;
    const int q0 = blockIdx.x * BQ;
    const int tid = threadIdx.x;
    const int tx = tid & 15, ty = tid >> 4;
    const float scale = 0.08838834764831845f;   // 1/sqrt(128)

    // load Q tile (pre-scaled)
#pragma unroll
    for (int i = 0; i < 8; i++) {
        int idx4 = tid + i * 256;
        int r = idx4 >> 5, d4 = idx4 & 31;
        float4 v = *(const float4*)(g_q + (size_t)(q0 + r) * DIM + h * DH + d4 * 4);
        float* dst = Qs + r * QSTR + d4 * 4;
        dst[0] = v.x * scale; dst[1] = v.y * scale;
        dst[2] = v.z * scale; dst[3] = v.w * scale;
    }

    float m[4], l[4], acc[4][8];
#pragma unroll
    for (int i = 0; i < 4; i++) {
        m[i] = -1e30f; l[i] = 0.f;
#pragma unroll
        for (int j = 0; j < 8; j++) acc[i][j] = 0.f;
    }

    for (int kt = 0; kt < SEQ / BKV; kt++) {
        __syncthreads();   // prior-iter consumers done; also fences Q load on iter 0
        const int t0 = kt * BKV;
#pragma unroll
        for (int i = 0; i < 8; i++) {
            int idx4 = tid + i * 256;
            int t = idx4 >> 5, d4 = idx4 & 31;
            float4 kvv = *(const float4*)(g_k + (size_t)(t0 + t) * DIM + h * DH + d4 * 4);
            float* kd = Ks + t * KSTR + d4 * 4;
            kd[0] = kvv.x; kd[1] = kvv.y; kd[2] = kvv.z; kd[3] = kvv.w;
            float4 vv = *(const float4*)(g_v + (size_t)(t0 + t) * DIM + h * DH + d4 * 4);
            *(float4*)(Vs + t * VSTR + d4 * 4) = vv;
        }
        __syncthreads();

        // scores: 4x4 per thread, rows ty+i*16, cols tx+j*16
        float s4[4][4];
#pragma unroll
        for (int i = 0; i < 4; i++)
#pragma unroll
            for (int j = 0; j < 4; j++) s4[i][j] = 0.f;

#pragma unroll 4
        for (int d = 0; d < DH; d++) {
            float qv[4], kv[4];
#pragma unroll
            for (int i = 0; i < 4; i++) qv[i] = Qs[(ty + i * 16) * QSTR + d];
#pragma unroll
            for (int j = 0; j < 4; j++) kv[j] = Ks[(tx + j * 16) * KSTR + d];
#pragma unroll
            for (int i = 0; i < 4; i++)
#pragma unroll
                for (int j = 0; j < 4; j++)
                    s4[i][j] += qv[i] * kv[j];
        }

        // online softmax update (row reductions across the 16 tx lanes)
#pragma unroll
        for (int i = 0; i < 4; i++) {
            float mx = fmaxf(fmaxf(s4[i][0], s4[i][1]), fmaxf(s4[i][2], s4[i][3]));
#pragma unroll
            for (int off = 1; off < 16; off <<= 1)
                mx = fmaxf(mx, __shfl_xor_sync(0xffffffffu, mx, off));
            float mnew = fmaxf(m[i], mx);
            float alpha = __expf(m[i] - mnew);
            float sum = 0.f;
#pragma unroll
            for (int j = 0; j < 4; j++) {
                float p = __expf(s4[i][j] - mnew);
                Ps[(ty + i * 16) * PSTR + tx + j * 16] = p;
                sum += p;
            }
#pragma unroll
            for (int off = 1; off < 16; off <<= 1)
                sum += __shfl_xor_sync(0xffffffffu, sum, off);
            l[i] = l[i] * alpha + sum;
            m[i] = mnew;
#pragma unroll
            for (int c = 0; c < 8; c++) acc[i][c] *= alpha;
        }
        __syncthreads();

        // PV accumulate: O[r][c] += P[r][t] * V[t][c], cols c = tx + j*16
#pragma unroll 2
        for (int t = 0; t < BKV; t++) {
            float pv[4];
#pragma unroll
            for (int i = 0; i < 4; i++) pv[i] = Ps[(ty + i * 16) * PSTR + t];
#pragma unroll
            for (int j = 0; j < 8; j++) {
                float vv = Vs[t * VSTR + tx + j * 16];
#pragma unroll
                for (int i = 0; i < 4; i++) acc[i][j] += pv[i] * vv;
            }
        }
    }

#pragma unroll
    for (int i = 0; i < 4; i++) {
        float inv = 1.0f / l[i];
        int r = q0 + ty + i * 16;
#pragma unroll
        for (int j = 0; j < 8; j++)
            g_att[(size_t)r * DIM + h * DH + tx + j * 16] = acc[i][j] * inv;
    }
}

// ---------------------------------------------------------------------------
// Host launch
// ---------------------------------------------------------------------------
extern "C" void kernel_launch(void* const* d_in, const int* in_sizes, int n_in,
                              void* d_out, int out_size) {
    const float* x  = (const float*)d_in[0];
    const float* fc = (const float*)d_in[1];
    const float* fs = (const float*)d_in[2];
    const float* Wq = (const float*)d_in[3];
    const float* bq = (const float*)d_in[4];
    const float* Wk = (const float*)d_in[5];
    const float* bk = (const float*)d_in[6];
    const float* Wv = (const float*)d_in[7];
    const float* bv = (const float*)d_in[8];
    const float* Wo = (const float*)d_in[9];
    const float* bo = (const float*)d_in[10];
    const float* gq = (const float*)d_in[11];
    const float* gk = (const float*)d_in[12];
    float* out = (float*)d_out;

    float *q, *k, *v, *att;
    cudaGetSymbolAddress((void**)&q,   g_q);
    cudaGetSymbolAddress((void**)&k,   g_k);
    cudaGetSymbolAddress((void**)&v,   g_v);
    cudaGetSymbolAddress((void**)&att, g_att);

    cudaFuncSetAttribute(attn_kernel, cudaFuncAttributeMaxDynamicSharedMemorySize,
                         ATTN_SMEM);

    dim3 gemm_grid(DIM / GBN, SEQ / GBM);
    gemm_bias_kernel<<<gemm_grid, 256>>>(x, Wq, bq, q);
    gemm_bias_kernel<<<gemm_grid, 256>>>(x, Wk, bk, k);
    gemm_bias_kernel<<<gemm_grid, 256>>>(x, Wv, bv, v);
    rmsnorm_rope_kernel<<<SEQ, 256>>>(fc, fs, gq, gk);
    attn_kernel<<<dim3(SEQ / BQ, NH), 256, ATTN_SMEM>>>();
    gemm_bias_kernel<<<gemm_grid, 256>>>(att, Wo, bo, out);
}

// round 2
// speedup vs baseline: 1.6033x; 1.6033x over previous
#include <cuda_runtime.h>
#include <math.h>

#define SEQ 4096
#define DIM 2048
#define NH 16
#define DH 128

// Scratch (static device arrays — no allocations allowed)
__device__ float g_q[SEQ * DIM];
__device__ float g_k[SEQ * DIM];
__device__ float g_v[SEQ * DIM];
__device__ float g_att[SEQ * DIM];

// ---------------------------------------------------------------------------
// tf32 tensor-core GEMM: C[4096,2048] = A @ W + bias
// 128x128 block tile, K-tile 16, double-buffered smem, 8 warps (32x64 each),
// mma.sync.m16n8k8 tf32. Conflict-free strides: A=20, B=136.
// ---------------------------------------------------------------------------
#define ASTR 20
#define BSTR 136

__device__ __forceinline__ unsigned tf32r(float f) {
    unsigned u;
    asm("cvt.rna.tf32.f32 %0, %1;" : "=r"(u) : "f"(f));
    return u;
}

__device__ __forceinline__ void mma_tf32(float* c, const unsigned* a, const unsigned* b) {
    asm volatile(
        "mma.sync.aligned.m16n8k8.row.col.f32.tf32.tf32.f32 "
        "{%0,%1,%2,%3}, {%4,%5,%6,%7}, {%8,%9}, {%0,%1,%2,%3};\n"
        : "+f"(c[0]), "+f"(c[1]), "+f"(c[2]), "+f"(c[3])
        : "r"(a[0]), "r"(a[1]), "r"(a[2]), "r"(a[3]), "r"(b[0]), "r"(b[1]));
}

__global__ __launch_bounds__(256)
void gemm_bias_kernel(const float* __restrict__ A, const float* __restrict__ W,
                      const float* __restrict__ bias, float* __restrict__ C) {
    __shared__ unsigned As[2][128][ASTR];
    __shared__ unsigned Bs[2][16][BSTR];

    const int tid = threadIdx.x;
    const int lane = tid & 31, wid = tid >> 5;
    const int wm = (wid & 3) * 32;      // warp M offset (4 warps x 32)
    const int wn = (wid >> 2) * 64;     // warp N offset (2 warps x 64)
    const int g = lane >> 2, t = lane & 3;

    const float* Ag = A + (size_t)(blockIdx.y * 128) * DIM;
    const float* Bg = W + blockIdx.x * 128;

    const int ar = tid >> 2, ak = (tid & 3) * 4;   // A: 64 rows/pass, 2 passes
    const int br = tid >> 5, bn = (tid & 31) * 4;  // B: 8 rows/pass, 2 passes

    float c[2][8][4];
#pragma unroll
    for (int mt = 0; mt < 2; mt++)
#pragma unroll
        for (int nt = 0; nt < 8; nt++)
#pragma unroll
            for (int i = 0; i < 4; i++) c[mt][nt][i] = 0.f;

    // prologue: load + store tile 0
    float4 pa0 = *(const float4*)(Ag + (size_t)ar * DIM + ak);
    float4 pa1 = *(const float4*)(Ag + (size_t)(ar + 64) * DIM + ak);
    float4 pb0 = *(const float4*)(Bg + (size_t)br * DIM + bn);
    float4 pb1 = *(const float4*)(Bg + (size_t)(br + 8) * DIM + bn);
    {
        uint4 u;
        u.x = tf32r(pa0.x); u.y = tf32r(pa0.y); u.z = tf32r(pa0.z); u.w = tf32r(pa0.w);
        *(uint4*)&As[0][ar][ak] = u;
        u.x = tf32r(pa1.x); u.y = tf32r(pa1.y); u.z = tf32r(pa1.z); u.w = tf32r(pa1.w);
        *(uint4*)&As[0][ar + 64][ak] = u;
        u.x = tf32r(pb0.x); u.y = tf32r(pb0.y); u.z = tf32r(pb0.z); u.w = tf32r(pb0.w);
        *(uint4*)&Bs[0][br][bn] = u;
        u.x = tf32r(pb1.x); u.y = tf32r(pb1.y); u.z = tf32r(pb1.z); u.w = tf32r(pb1.w);
        *(uint4*)&Bs[0][br + 8][bn] = u;
    }

    int buf = 0;
    for (int k0 = 0; k0 < DIM; k0 += 16) {
        __syncthreads();
        const bool more = (k0 + 16 < DIM);
        if (more) {
            const float* Ap = Ag + k0 + 16;
            const float* Bp = Bg + (size_t)(k0 + 16) * DIM;
            pa0 = *(const float4*)(Ap + (size_t)ar * DIM + ak);
            pa1 = *(const float4*)(Ap + (size_t)(ar + 64) * DIM + ak);
            pb0 = *(const float4*)(Bp + (size_t)br * DIM + bn);
            pb1 = *(const float4*)(Bp + (size_t)(br + 8) * DIM + bn);
        }

#pragma unroll
        for (int kk = 0; kk < 16; kk += 8) {
            unsigned a[2][4], b[8][2];
#pragma unroll
            for (int mt = 0; mt < 2; mt++) {
                int r0 = wm + mt * 16 + g;
                a[mt][0] = As[buf][r0][kk + t];
                a[mt][1] = As[buf][r0 + 8][kk + t];
                a[mt][2] = As[buf][r0][kk + t + 4];
                a[mt][3] = As[buf][r0 + 8][kk + t + 4];
            }
#pragma unroll
            for (int nt = 0; nt < 8; nt++) {
                int cc = wn + nt * 8 + g;
                b[nt][0] = Bs[buf][kk + t][cc];
                b[nt][1] = Bs[buf][kk + t + 4][cc];
            }
#pragma unroll
            for (int mt = 0; mt < 2; mt++)
#pragma unroll
                for (int nt = 0; nt < 8; nt++)
                    mma_tf32(c[mt][nt], a[mt], b[nt]);
        }

        if (more) {
            int nb = buf ^ 1;
            uint4 u;
            u.x = tf32r(pa0.x); u.y = tf32r(pa0.y); u.z = tf32r(pa0.z); u.w = tf32r(pa0.w);
            *(uint4*)&As[nb][ar][ak] = u;
            u.x = tf32r(pa1.x); u.y = tf32r(pa1.y); u.z = tf32r(pa1.z); u.w = tf32r(pa1.w);
            *(uint4*)&As[nb][ar + 64][ak] = u;
            u.x = tf32r(pb0.x); u.y = tf32r(pb0.y); u.z = tf32r(pb0.z); u.w = tf32r(pb0.w);
            *(uint4*)&Bs[nb][br][bn] = u;
            u.x = tf32r(pb1.x); u.y = tf32r(pb1.y); u.z = tf32r(pb1.z); u.w = tf32r(pb1.w);
            *(uint4*)&Bs[nb][br + 8][bn] = u;
            buf = nb;
        }
    }

    // epilogue
    const int rowB = blockIdx.y * 128 + wm;
    const int colB = blockIdx.x * 128 + wn;
#pragma unroll
    for (int mt = 0; mt < 2; mt++) {
        int r0 = rowB + mt * 16 + g;
#pragma unroll
        for (int nt = 0; nt < 8; nt++) {
            int col = colB + nt * 8 + 2 * t;
            float b0 = bias[col], b1 = bias[col + 1];
            float2 v;
            v.x = c[mt][nt][0] + b0; v.y = c[mt][nt][1] + b1;
            *(float2*)(C + (size_t)r0 * DIM + col) = v;
            v.x = c[mt][nt][2] + b0; v.y = c[mt][nt][3] + b1;
            *(float2*)(C + (size_t)(r0 + 8) * DIM + col) = v;
        }
    }
}

// ---------------------------------------------------------------------------
// RMSNorm (over full DIM=2048, before head split) + RoPE (interleaved pairs)
// ---------------------------------------------------------------------------
__global__ __launch_bounds__(256)
void rmsnorm_rope_kernel(const float* __restrict__ fc, const float* __restrict__ fs,
                         const float* __restrict__ gq, const float* __restrict__ gk) {
    const int s = blockIdx.x;
    const int tid = threadIdx.x;
    float* qrow = g_q + (size_t)s * DIM;
    float* krow = g_k + (size_t)s * DIM;

    float q1[4], q2[4], k1[4], k2[4];
    float sq = 0.f, sk = 0.f;
#pragma unroll
    for (int j = 0; j < 4; j++) {
        int p = tid + j * 256;
        int h = p >> 6, jj = p & 63;
        int i1 = h * DH + 2 * jj;
        float2 qv = *(const float2*)(qrow + i1);
        float2 kv = *(const float2*)(krow + i1);
        q1[j] = qv.x; q2[j] = qv.y; k1[j] = kv.x; k2[j] = kv.y;
        sq += qv.x * qv.x + qv.y * qv.y;
        sk += kv.x * kv.x + kv.y * kv.y;
    }
#pragma unroll
    for (int off = 16; off > 0; off >>= 1) {
        sq += __shfl_xor_sync(0xffffffffu, sq, off);
        sk += __shfl_xor_sync(0xffffffffu, sk, off);
    }
    __shared__ float sh[16];
    if ((tid & 31) == 0) { sh[tid >> 5] = sq; sh[8 + (tid >> 5)] = sk; }
    __syncthreads();
    float tq = 0.f, tk = 0.f;
#pragma unroll
    for (int w = 0; w < 8; w++) { tq += sh[w]; tk += sh[8 + w]; }
    const float rq = rsqrtf(tq * (1.0f / DIM) + 1e-5f);
    const float rk = rsqrtf(tk * (1.0f / DIM) + 1e-5f);

#pragma unroll
    for (int j = 0; j < 4; j++) {
        int p = tid + j * 256;
        int h = p >> 6, jj = p & 63;
        int i1 = h * DH + 2 * jj;
        float c = fc[(size_t)s * DH + 2 * jj];
        float sn = fs[(size_t)s * DH + 2 * jj + 1];
        float x1 = q1[j] * rq * gq[i1];
        float x2 = q2[j] * rq * gq[i1 + 1];
        float2 oq; oq.x = x1 * c - x2 * sn; oq.y = x1 * sn + x2 * c;
        *(float2*)(qrow + i1) = oq;
        x1 = k1[j] * rk * gk[i1];
        x2 = k2[j] * rk * gk[i1 + 1];
        float2 ok; ok.x = x1 * c - x2 * sn; ok.y = x1 * sn + x2 * c;
        *(float2*)(krow + i1) = ok;
    }
}

// ---------------------------------------------------------------------------
// Flash attention (fp32, online softmax). One block per (head, 64-query tile).
// ---------------------------------------------------------------------------
#define BQ 64
#define BKV 64
#define QSTR 129
#define KSTR 129
#define VSTR 128
#define PSTR 80
#define ATTN_SMEM ((BQ * QSTR + BKV * KSTR + BKV * VSTR + BQ * PSTR) * 4)

__global__ __launch_bounds__(256)
void attn_kernel() {
    extern __shared__ float sm[];
    float* Qs = sm;
    float* Ks = Qs + BQ * QSTR;
    float* Vs = Ks + BKV * KSTR;
    float* Ps = Vs + BKV * VSTR;

    const int h = blockIdx.y;
    const int q0 = blockIdx.x * BQ;
    const int tid = threadIdx.x;
    const int tx = tid & 15, ty = tid >> 4;
    const float scale = 0.08838834764831845f;

#pragma unroll
    for (int i = 0; i < 8; i++) {
        int idx4 = tid + i * 256;
        int r = idx4 >> 5, d4 = idx4 & 31;
        float4 v = *(const float4*)(g_q + (size_t)(q0 + r) * DIM + h * DH + d4 * 4);
        float* dst = Qs + r * QSTR + d4 * 4;
        dst[0] = v.x * scale; dst[1] = v.y * scale;
        dst[2] = v.z * scale; dst[3] = v.w * scale;
    }

    float m[4], l[4], acc[4][8];
#pragma unroll
    for (int i = 0; i < 4; i++) {
        m[i] = -1e30f; l[i] = 0.f;
#pragma unroll
        for (int j = 0; j < 8; j++) acc[i][j] = 0.f;
    }

    for (int kt = 0; kt < SEQ / BKV; kt++) {
        __syncthreads();
        const int t0 = kt * BKV;
#pragma unroll
        for (int i = 0; i < 8; i++) {
            int idx4 = tid + i * 256;
            int t = idx4 >> 5, d4 = idx4 & 31;
            float4 kvv = *(const float4*)(g_k + (size_t)(t0 + t) * DIM + h * DH + d4 * 4);
            float* kd = Ks + t * KSTR + d4 * 4;
            kd[0] = kvv.x; kd[1] = kvv.y; kd[2] = kvv.z; kd[3] = kvv.w;
            float4 vv = *(const float4*)(g_v + (size_t)(t0 + t) * DIM + h * DH + d4 * 4);
            *(float4*)(Vs + t * VSTR + d4 * 4) = vv;
        }
        __syncthreads();

        float s4[4][4];
#pragma unroll
        for (int i = 0; i < 4; i++)
#pragma unroll
            for (int j = 0; j < 4; j++) s4[i][j] = 0.f;

#pragma unroll 4
        for (int d = 0; d < DH; d++) {
            float qv[4], kv[4];
#pragma unroll
            for (int i = 0; i < 4; i++) qv[i] = Qs[(ty + i * 16) * QSTR + d];
#pragma unroll
            for (int j = 0; j < 4; j++) kv[j] = Ks[(tx + j * 16) * KSTR + d];
#pragma unroll
            for (int i = 0; i < 4; i++)
#pragma unroll
                for (int j = 0; j < 4; j++)
                    s4[i][j] += qv[i] * kv[j];
        }

#pragma unroll
        for (int i = 0; i < 4; i++) {
            float mx = fmaxf(fmaxf(s4[i][0], s4[i][1]), fmaxf(s4[i][2], s4[i][3]));
#pragma unroll
            for (int off = 1; off < 16; off <<= 1)
                mx = fmaxf(mx, __shfl_xor_sync(0xffffffffu, mx, off));
            float mnew = fmaxf(m[i], mx);
            float alpha = __expf(m[i] - mnew);
            float sum = 0.f;
#pragma unroll
            for (int j = 0; j < 4; j++) {
                float p = __expf(s4[i][j] - mnew);
                Ps[(ty + i * 16) * PSTR + tx + j * 16] = p;
                sum += p;
            }
#pragma unroll
            for (int off = 1; off < 16; off <<= 1)
                sum += __shfl_xor_sync(0xffffffffu, sum, off);
            l[i] = l[i] * alpha + sum;
            m[i] = mnew;
#pragma unroll
            for (int c = 0; c < 8; c++) acc[i][c] *= alpha;
        }
        __syncthreads();

#pragma unroll 2
        for (int t = 0; t < BKV; t++) {
            float pv[4];
#pragma unroll
            for (int i = 0; i < 4; i++) pv[i] = Ps[(ty + i * 16) * PSTR + t];
#pragma unroll
            for (int j = 0; j < 8; j++) {
                float vv = Vs[t * VSTR + tx + j * 16];
#pragma unroll
                for (int i = 0; i < 4; i++) acc[i][j] += pv[i] * vv;
            }
        }
    }

#pragma unroll
    for (int i = 0; i < 4; i++) {
        float inv = 1.0f / l[i];
        int r = q0 + ty + i * 16;
#pragma unroll
        for (int j = 0; j < 8; j++)
            g_att[(size_t)r * DIM + h * DH + tx + j * 16] = acc[i][j] * inv;
    }
}

// ---------------------------------------------------------------------------
// Host launch
// ---------------------------------------------------------------------------
extern "C" void kernel_launch(void* const* d_in, const int* in_sizes, int n_in,
                              void* d_out, int out_size) {
    const float* x  = (const float*)d_in[0];
    const float* fc = (const float*)d_in[1];
    const float* fs = (const float*)d_in[2];
    const float* Wq = (const float*)d_in[3];
    const float* bq = (const float*)d_in[4];
    const float* Wk = (const float*)d_in[5];
    const float* bk = (const float*)d_in[6];
    const float* Wv = (const float*)d_in[7];
    const float* bv = (const float*)d_in[8];
    const float* Wo = (const float*)d_in[9];
    const float* bo = (const float*)d_in[10];
    const float* gq = (const float*)d_in[11];
    const float* gk = (const float*)d_in[12];
    float* out = (float*)d_out;

    float *q, *k, *v, *att;
    cudaGetSymbolAddress((void**)&q,   g_q);
    cudaGetSymbolAddress((void**)&k,   g_k);
    cudaGetSymbolAddress((void**)&v,   g_v);
    cudaGetSymbolAddress((void**)&att, g_att);

    cudaFuncSetAttribute(attn_kernel, cudaFuncAttributeMaxDynamicSharedMemorySize,
                         ATTN_SMEM);

    dim3 gemm_grid(DIM / 128, SEQ / 128);
    gemm_bias_kernel<<<gemm_grid, 256>>>(x, Wq, bq, q);
    gemm_bias_kernel<<<gemm_grid, 256>>>(x, Wk, bk, k);
    gemm_bias_kernel<<<gemm_grid, 256>>>(x, Wv, bv, v);
    rmsnorm_rope_kernel<<<SEQ, 256>>>(fc, fs, gq, gk);
    attn_kernel<<<dim3(SEQ / BQ, NH), 256, ATTN_SMEM>>>();
    gemm_bias_kernel<<<gemm_grid, 256>>>(att, Wo, bo, out);
}

// round 4
// speedup vs baseline: 3.9731x; 2.4781x over previous
#include <cuda_runtime.h>
#include <math.h>

#define SEQ 4096
#define DIM 2048
#define NH 16
#define DH 128

// Scratch (static device arrays — no allocations allowed)
__device__ float g_q[SEQ * DIM];
__device__ float g_k[SEQ * DIM];
__device__ float g_v[SEQ * DIM];
__device__ float g_att[SEQ * DIM];

__device__ __forceinline__ unsigned tf32r(float f) {
    unsigned u;
    asm("cvt.rna.tf32.f32 %0, %1;" : "=r"(u) : "f"(f));
    return u;
}

__device__ __forceinline__ void mma_tf32(float* c, const unsigned* a, const unsigned* b) {
    asm volatile(
        "mma.sync.aligned.m16n8k8.row.col.f32.tf32.tf32.f32 "
        "{%0,%1,%2,%3}, {%4,%5,%6,%7}, {%8,%9}, {%0,%1,%2,%3};\n"
        : "+f"(c[0]), "+f"(c[1]), "+f"(c[2]), "+f"(c[3])
        : "r"(a[0]), "r"(a[1]), "r"(a[2]), "r"(a[3]), "r"(b[0]), "r"(b[1]));
}

// ---------------------------------------------------------------------------
// tf32 tensor-core GEMM: C[4096,2048] = A @ W + bias  (unchanged — passing)
// ---------------------------------------------------------------------------
#define ASTR 20
#define BSTR 136

__global__ __launch_bounds__(256)
void gemm_bias_kernel(const float* __restrict__ A, const float* __restrict__ W,
                      const float* __restrict__ bias, float* __restrict__ C) {
    __shared__ unsigned As[2][128][ASTR];
    __shared__ unsigned Bs[2][16][BSTR];

    const int tid = threadIdx.x;
    const int lane = tid & 31, wid = tid >> 5;
    const int wm = (wid & 3) * 32;
    const int wn = (wid >> 2) * 64;
    const int g = lane >> 2, t = lane & 3;

    const float* Ag = A + (size_t)(blockIdx.y * 128) * DIM;
    const float* Bg = W + blockIdx.x * 128;

    const int ar = tid >> 2, ak = (tid & 3) * 4;
    const int br = tid >> 5, bn = (tid & 31) * 4;

    float c[2][8][4];
#pragma unroll
    for (int mt = 0; mt < 2; mt++)
#pragma unroll
        for (int nt = 0; nt < 8; nt++)
#pragma unroll
            for (int i = 0; i < 4; i++) c[mt][nt][i] = 0.f;

    float4 pa0 = *(const float4*)(Ag + (size_t)ar * DIM + ak);
    float4 pa1 = *(const float4*)(Ag + (size_t)(ar + 64) * DIM + ak);
    float4 pb0 = *(const float4*)(Bg + (size_t)br * DIM + bn);
    float4 pb1 = *(const float4*)(Bg + (size_t)(br + 8) * DIM + bn);
    {
        uint4 u;
        u.x = tf32r(pa0.x); u.y = tf32r(pa0.y); u.z = tf32r(pa0.z); u.w = tf32r(pa0.w);
        *(uint4*)&As[0][ar][ak] = u;
        u.x = tf32r(pa1.x); u.y = tf32r(pa1.y); u.z = tf32r(pa1.z); u.w = tf32r(pa1.w);
        *(uint4*)&As[0][ar + 64][ak] = u;
        u.x = tf32r(pb0.x); u.y = tf32r(pb0.y); u.z = tf32r(pb0.z); u.w = tf32r(pb0.w);
        *(uint4*)&Bs[0][br][bn] = u;
        u.x = tf32r(pb1.x); u.y = tf32r(pb1.y); u.z = tf32r(pb1.z); u.w = tf32r(pb1.w);
        *(uint4*)&Bs[0][br + 8][bn] = u;
    }

    int buf = 0;
    for (int k0 = 0; k0 < DIM; k0 += 16) {
        __syncthreads();
        const bool more = (k0 + 16 < DIM);
        if (more) {
            const float* Ap = Ag + k0 + 16;
            const float* Bp = Bg + (size_t)(k0 + 16) * DIM;
            pa0 = *(const float4*)(Ap + (size_t)ar * DIM + ak);
            pa1 = *(const float4*)(Ap + (size_t)(ar + 64) * DIM + ak);
            pb0 = *(const float4*)(Bp + (size_t)br * DIM + bn);
            pb1 = *(const float4*)(Bp + (size_t)(br + 8) * DIM + bn);
        }

#pragma unroll
        for (int kk = 0; kk < 16; kk += 8) {
            unsigned a[2][4], b[8][2];
#pragma unroll
            for (int mt = 0; mt < 2; mt++) {
                int r0 = wm + mt * 16 + g;
                a[mt][0] = As[buf][r0][kk + t];
                a[mt][1] = As[buf][r0 + 8][kk + t];
                a[mt][2] = As[buf][r0][kk + t + 4];
                a[mt][3] = As[buf][r0 + 8][kk + t + 4];
            }
#pragma unroll
            for (int nt = 0; nt < 8; nt++) {
                int cc = wn + nt * 8 + g;
                b[nt][0] = Bs[buf][kk + t][cc];
                b[nt][1] = Bs[buf][kk + t + 4][cc];
            }
#pragma unroll
            for (int mt = 0; mt < 2; mt++)
#pragma unroll
                for (int nt = 0; nt < 8; nt++)
                    mma_tf32(c[mt][nt], a[mt], b[nt]);
        }

        if (more) {
            int nb = buf ^ 1;
            uint4 u;
            u.x = tf32r(pa0.x); u.y = tf32r(pa0.y); u.z = tf32r(pa0.z); u.w = tf32r(pa0.w);
            *(uint4*)&As[nb][ar][ak] = u;
            u.x = tf32r(pa1.x); u.y = tf32r(pa1.y); u.z = tf32r(pa1.z); u.w = tf32r(pa1.w);
            *(uint4*)&As[nb][ar + 64][ak] = u;
            u.x = tf32r(pb0.x); u.y = tf32r(pb0.y); u.z = tf32r(pb0.z); u.w = tf32r(pb0.w);
            *(uint4*)&Bs[nb][br][bn] = u;
            u.x = tf32r(pb1.x); u.y = tf32r(pb1.y); u.z = tf32r(pb1.z); u.w = tf32r(pb1.w);
            *(uint4*)&Bs[nb][br + 8][bn] = u;
            buf = nb;
        }
    }

    const int rowB = blockIdx.y * 128 + wm;
    const int colB = blockIdx.x * 128 + wn;
#pragma unroll
    for (int mt = 0; mt < 2; mt++) {
        int r0 = rowB + mt * 16 + g;
#pragma unroll
        for (int nt = 0; nt < 8; nt++) {
            int col = colB + nt * 8 + 2 * t;
            float b0 = bias[col], b1 = bias[col + 1];
            float2 v;
            v.x = c[mt][nt][0] + b0; v.y = c[mt][nt][1] + b1;
            *(float2*)(C + (size_t)r0 * DIM + col) = v;
            v.x = c[mt][nt][2] + b0; v.y = c[mt][nt][3] + b1;
            *(float2*)(C + (size_t)(r0 + 8) * DIM + col) = v;
        }
    }
}

// ---------------------------------------------------------------------------
// RMSNorm + RoPE (unchanged)
// ---------------------------------------------------------------------------
__global__ __launch_bounds__(256)
void rmsnorm_rope_kernel(const float* __restrict__ fc, const float* __restrict__ fs,
                         const float* __restrict__ gq, const float* __restrict__ gk) {
    const int s = blockIdx.x;
    const int tid = threadIdx.x;
    float* qrow = g_q + (size_t)s * DIM;
    float* krow = g_k + (size_t)s * DIM;

    float q1[4], q2[4], k1[4], k2[4];
    float sq = 0.f, sk = 0.f;
#pragma unroll
    for (int j = 0; j < 4; j++) {
        int p = tid + j * 256;
        int h = p >> 6, jj = p & 63;
        int i1 = h * DH + 2 * jj;
        float2 qv = *(const float2*)(qrow + i1);
        float2 kv = *(const float2*)(krow + i1);
        q1[j] = qv.x; q2[j] = qv.y; k1[j] = kv.x; k2[j] = kv.y;
        sq += qv.x * qv.x + qv.y * qv.y;
        sk += kv.x * kv.x + kv.y * kv.y;
    }
#pragma unroll
    for (int off = 16; off > 0; off >>= 1) {
        sq += __shfl_xor_sync(0xffffffffu, sq, off);
        sk += __shfl_xor_sync(0xffffffffu, sk, off);
    }
    __shared__ float sh[16];
    if ((tid & 31) == 0) { sh[tid >> 5] = sq; sh[8 + (tid >> 5)] = sk; }
    __syncthreads();
    float tq = 0.f, tk = 0.f;
#pragma unroll
    for (int w = 0; w < 8; w++) { tq += sh[w]; tk += sh[8 + w]; }
    const float rq = rsqrtf(tq * (1.0f / DIM) + 1e-5f);
    const float rk = rsqrtf(tk * (1.0f / DIM) + 1e-5f);

#pragma unroll
    for (int j = 0; j < 4; j++) {
        int p = tid + j * 256;
        int h = p >> 6, jj = p & 63;
        int i1 = h * DH + 2 * jj;
        float c = fc[(size_t)s * DH + 2 * jj];
        float sn = fs[(size_t)s * DH + 2 * jj + 1];
        float x1 = q1[j] * rq * gq[i1];
        float x2 = q2[j] * rq * gq[i1 + 1];
        float2 oq; oq.x = x1 * c - x2 * sn; oq.y = x1 * sn + x2 * c;
        *(float2*)(qrow + i1) = oq;
        x1 = k1[j] * rk * gk[i1];
        x2 = k2[j] * rk * gk[i1 + 1];
        float2 ok; ok.x = x1 * c - x2 * sn; ok.y = x1 * sn + x2 * c;
        *(float2*)(krow + i1) = ok;
    }
}

// ---------------------------------------------------------------------------
// Flash attention, tf32 tensor-core. BQ=128, BKV=64, 8 warps (16 Q rows each).
// Strides: Q/K 132, P 68 (=4 mod 32), V 136 (=8 mod 32) -> conflict-free.
// ---------------------------------------------------------------------------
#define BQ 128
#define BKV 64
#define QS 132
#define KS 132
#define VS 136
#define PS 68
#define ATTN_SMEM ((BQ * QS + BKV * KS + BKV * VS + BQ * PS) * 4)

__global__ __launch_bounds__(256, 1)
void attn_kernel() {
    extern __shared__ unsigned smu[];
    unsigned* Qs = smu;
    unsigned* Ks = Qs + BQ * QS;
    unsigned* Vs = Ks + BKV * KS;
    unsigned* Ps = Vs + BKV * VS;

    const int h = blockIdx.y;
    const int q0 = blockIdx.x * BQ;
    const int tid = threadIdx.x;
    const int lane = tid & 31, wid = tid >> 5;
    const int g = lane >> 2, t = lane & 3;
    const int rbase = wid * 16;
    const float scale = 0.08838834764831845f;   // 1/sqrt(128)

    // load Q tile (pre-scaled, tf32): 128 rows x 32 float4
#pragma unroll
    for (int i = 0; i < 16; i++) {
        int idx = tid + i * 256;               // 4096 float4
        int r = idx >> 5, c4 = (idx & 31) * 4;
        float4 v = *(const float4*)(g_q + (size_t)(q0 + r) * DIM + h * DH + c4);
        unsigned* dst = Qs + r * QS + c4;
        dst[0] = tf32r(v.x * scale); dst[1] = tf32r(v.y * scale);
        dst[2] = tf32r(v.z * scale); dst[3] = tf32r(v.w * scale);
    }

    float o[16][4];
#pragma unroll
    for (int nt = 0; nt < 16; nt++)
#pragma unroll
        for (int i = 0; i < 4; i++) o[nt][i] = 0.f;
    float m0 = -1e30f, m1 = -1e30f, l0 = 0.f, l1 = 0.f;

    for (int kt = 0; kt < SEQ / BKV; kt++) {
        __syncthreads();
        const int tok0 = kt * BKV;
        // K and V tiles: 64 rows x 32 float4 EACH (full DH=128)
#pragma unroll
        for (int i = 0; i < 8; i++) {
            int idx = tid + i * 256;           // 2048 float4 per tensor
            int r = idx >> 5, c4 = (idx & 31) * 4;
            float4 kv = *(const float4*)(g_k + (size_t)(tok0 + r) * DIM + h * DH + c4);
            unsigned* kd = Ks + r * KS + c4;
            kd[0] = tf32r(kv.x); kd[1] = tf32r(kv.y); kd[2] = tf32r(kv.z); kd[3] = tf32r(kv.w);
            float4 vv = *(const float4*)(g_v + (size_t)(tok0 + r) * DIM + h * DH + c4);
            unsigned* vd = Vs + r * VS + c4;
            vd[0] = tf32r(vv.x); vd[1] = tf32r(vv.y); vd[2] = tf32r(vv.z); vd[3] = tf32r(vv.w);
        }
        __syncthreads();

        // ---- S = Q K^T (16x64 per warp) ----
        float s[8][4];
#pragma unroll
        for (int nt = 0; nt < 8; nt++)
#pragma unroll
            for (int i = 0; i < 4; i++) s[nt][i] = 0.f;

#pragma unroll
        for (int kk = 0; kk < DH; kk += 8) {
            unsigned a[4];
            a[0] = Qs[(rbase + g) * QS + kk + t];
            a[1] = Qs[(rbase + g + 8) * QS + kk + t];
            a[2] = Qs[(rbase + g) * QS + kk + t + 4];
            a[3] = Qs[(rbase + g + 8) * QS + kk + t + 4];
#pragma unroll
            for (int nt = 0; nt < 8; nt++) {
                unsigned b[2];
                b[0] = Ks[(nt * 8 + g) * KS + kk + t];
                b[1] = Ks[(nt * 8 + g) * KS + kk + t + 4];
                mma_tf32(s[nt], a, b);
            }
        }

        // ---- online softmax (rows rbase+g and rbase+g+8) ----
        float mx0 = -1e30f, mx1 = -1e30f;
#pragma unroll
        for (int nt = 0; nt < 8; nt++) {
            mx0 = fmaxf(mx0, fmaxf(s[nt][0], s[nt][1]));
            mx1 = fmaxf(mx1, fmaxf(s[nt][2], s[nt][3]));
        }
        mx0 = fmaxf(mx0, __shfl_xor_sync(0xffffffffu, mx0, 1));
        mx0 = fmaxf(mx0, __shfl_xor_sync(0xffffffffu, mx0, 2));
        mx1 = fmaxf(mx1, __shfl_xor_sync(0xffffffffu, mx1, 1));
        mx1 = fmaxf(mx1, __shfl_xor_sync(0xffffffffu, mx1, 2));

        float mn0 = fmaxf(m0, mx0), mn1 = fmaxf(m1, mx1);
        float al0 = __expf(m0 - mn0), al1 = __expf(m1 - mn1);
        float sum0 = 0.f, sum1 = 0.f;
#pragma unroll
        for (int nt = 0; nt < 8; nt++) {
            float p00 = __expf(s[nt][0] - mn0);
            float p01 = __expf(s[nt][1] - mn0);
            float p10 = __expf(s[nt][2] - mn1);
            float p11 = __expf(s[nt][3] - mn1);
            sum0 += p00 + p01; sum1 += p10 + p11;
            uint2 u0; u0.x = tf32r(p00); u0.y = tf32r(p01);
            *(uint2*)&Ps[(rbase + g) * PS + nt * 8 + 2 * t] = u0;
            uint2 u1; u1.x = tf32r(p10); u1.y = tf32r(p11);
            *(uint2*)&Ps[(rbase + g + 8) * PS + nt * 8 + 2 * t] = u1;
        }
        sum0 += __shfl_xor_sync(0xffffffffu, sum0, 1);
        sum0 += __shfl_xor_sync(0xffffffffu, sum0, 2);
        sum1 += __shfl_xor_sync(0xffffffffu, sum1, 1);
        sum1 += __shfl_xor_sync(0xffffffffu, sum1, 2);
        l0 = l0 * al0 + sum0; l1 = l1 * al1 + sum1;
        m0 = mn0; m1 = mn1;
#pragma unroll
        for (int nt = 0; nt < 16; nt++) {
            o[nt][0] *= al0; o[nt][1] *= al0;
            o[nt][2] *= al1; o[nt][3] *= al1;
        }
        __syncwarp();   // P written by this warp, read below by this warp

        // ---- O += P V (16x128 per warp) ----
#pragma unroll
        for (int kk = 0; kk < BKV; kk += 8) {
            unsigned a[4];
            a[0] = Ps[(rbase + g) * PS + kk + t];
            a[1] = Ps[(rbase + g + 8) * PS + kk + t];
            a[2] = Ps[(rbase + g) * PS + kk + t + 4];
            a[3] = Ps[(rbase + g + 8) * PS + kk + t + 4];
#pragma unroll
            for (int nt = 0; nt < 16; nt++) {
                unsigned b[2];
                b[0] = Vs[(kk + t) * VS + nt * 8 + g];
                b[1] = Vs[(kk + t + 4) * VS + nt * 8 + g];
                mma_tf32(o[nt], a, b);
            }
        }
    }

    // epilogue
    const float inv0 = 1.0f / l0, inv1 = 1.0f / l1;
    const int r0 = q0 + rbase + g, r1 = r0 + 8;
#pragma unroll
    for (int nt = 0; nt < 16; nt++) {
        int col = h * DH + nt * 8 + 2 * t;
        float2 w0; w0.x = o[nt][0] * inv0; w0.y = o[nt][1] * inv0;
        *(float2*)(g_att + (size_t)r0 * DIM + col) = w0;
        float2 w1; w1.x = o[nt][2] * inv1; w1.y = o[nt][3] * inv1;
        *(float2*)(g_att + (size_t)r1 * DIM + col) = w1;
    }
}

// ---------------------------------------------------------------------------
// Host launch
// ---------------------------------------------------------------------------
extern "C" void kernel_launch(void* const* d_in, const int* in_sizes, int n_in,
                              void* d_out, int out_size) {
    const float* x  = (const float*)d_in[0];
    const float* fc = (const float*)d_in[1];
    const float* fs = (const float*)d_in[2];
    const float* Wq = (const float*)d_in[3];
    const float* bq = (const float*)d_in[4];
    const float* Wk = (const float*)d_in[5];
    const float* bk = (const float*)d_in[6];
    const float* Wv = (const float*)d_in[7];
    const float* bv = (const float*)d_in[8];
    const float* Wo = (const float*)d_in[9];
    const float* bo = (const float*)d_in[10];
    const float* gq = (const float*)d_in[11];
    const float* gk = (const float*)d_in[12];
    float* out = (float*)d_out;

    float *q, *k, *v, *att;
    cudaGetSymbolAddress((void**)&q,   g_q);
    cudaGetSymbolAddress((void**)&k,   g_k);
    cudaGetSymbolAddress((void**)&v,   g_v);
    cudaGetSymbolAddress((void**)&att, g_att);

    cudaFuncSetAttribute(attn_kernel, cudaFuncAttributeMaxDynamicSharedMemorySize,
                         ATTN_SMEM);

    dim3 gemm_grid(DIM / 128, SEQ / 128);
    gemm_bias_kernel<<<gemm_grid, 256>>>(x, Wq, bq, q);
    gemm_bias_kernel<<<gemm_grid, 256>>>(x, Wk, bk, k);
    gemm_bias_kernel<<<gemm_grid, 256>>>(x, Wv, bv, v);
    rmsnorm_rope_kernel<<<SEQ, 256>>>(fc, fs, gq, gk);
    attn_kernel<<<dim3(SEQ / BQ, NH), 256, ATTN_SMEM>>>();
    gemm_bias_kernel<<<gemm_grid, 256>>>(att, Wo, bo, out);
}

// round 5
// speedup vs baseline: 4.4190x; 1.1122x over previous
#include <cuda_runtime.h>
#include <math.h>

#define SEQ 4096
#define DIM 2048
#define NH 16
#define DH 128

// Scratch (static device arrays — no allocations allowed)
__device__ float g_q[SEQ * DIM];
__device__ float g_k[SEQ * DIM];
__device__ float g_v[SEQ * DIM];
__device__ float g_att[SEQ * DIM];

__device__ __forceinline__ unsigned tf32r(float f) {
    unsigned u;
    asm("cvt.rna.tf32.f32 %0, %1;" : "=r"(u) : "f"(f));
    return u;
}

__device__ __forceinline__ void mma_tf32(float* c, const unsigned* a, const unsigned* b) {
    asm volatile(
        "mma.sync.aligned.m16n8k8.row.col.f32.tf32.tf32.f32 "
        "{%0,%1,%2,%3}, {%4,%5,%6,%7}, {%8,%9}, {%0,%1,%2,%3};\n"
        : "+f"(c[0]), "+f"(c[1]), "+f"(c[2]), "+f"(c[3])
        : "r"(a[0]), "r"(a[1]), "r"(a[2]), "r"(a[3]), "r"(b[0]), "r"(b[1]));
}

__device__ __forceinline__ void cpa16(float* dst, const float* src) {
    unsigned d = (unsigned)__cvta_generic_to_shared(dst);
    asm volatile("cp.async.cg.shared.global [%0], [%1], 16;\n" :: "r"(d), "l"(src));
}
#define CP_COMMIT() asm volatile("cp.async.commit_group;\n" ::: "memory")
#define CP_WAIT2()  asm volatile("cp.async.wait_group 2;\n" ::: "memory")

// ---------------------------------------------------------------------------
// tf32 GEMM, 4-stage cp.async pipeline.
// Block 128x256, BK=16, 8 warps (64x64 each). C = A @ W + bias.
// A stride 20 (banks: 20g+t all distinct), B stride 264 (=8 mod 32).
// Raw fp32 bits fed to tf32 MMA (HW truncation).
// ---------------------------------------------------------------------------
#define BM 128
#define BN 256
#define BK 16
#define AST 20
#define BST 264
#define ASTAGE (BM * AST)     // 2560 floats
#define BSTAGE (BK * BST)     // 4224 floats
#define GEMM_SMEM ((4 * ASTAGE + 4 * BSTAGE) * 4)   // 108544 bytes
#define NKT (DIM / BK)        // 128 k-tiles

__device__ __forceinline__ void gemm_issue(float* As, float* Bs, int kt,
                                           const float* Ag, const float* Bg, int tid) {
    const int stg = kt & 3;
    const int k0 = kt * BK;
    float* Ad = As + stg * ASTAGE;
    float* Bd = Bs + stg * BSTAGE;
#pragma unroll
    for (int i = 0; i < 2; i++) {           // A: 512 float4
        int idx = tid + i * 256;
        int r = idx >> 2, c = (idx & 3) * 4;
        cpa16(Ad + r * AST + c, Ag + (size_t)r * DIM + k0 + c);
    }
#pragma unroll
    for (int i = 0; i < 4; i++) {           // B: 1024 float4
        int idx = tid + i * 256;
        int r = idx >> 6, c = (idx & 63) * 4;
        cpa16(Bd + r * BST + c, Bg + (size_t)(k0 + r) * DIM + c);
    }
}

__global__ __launch_bounds__(256, 1)
void gemm_bias_kernel(const float* __restrict__ A, const float* __restrict__ W,
                      const float* __restrict__ bias, float* __restrict__ C) {
    extern __shared__ float gsm[];
    float* As = gsm;
    float* Bs = gsm + 4 * ASTAGE;

    const int tid = threadIdx.x;
    const int lane = tid & 31, wid = tid >> 5;
    const int wm = (wid & 1) * 64;          // 2 warps along M
    const int wn = (wid >> 1) * 64;         // 4 warps along N
    const int g = lane >> 2, t = lane & 3;

    const float* Ag = A + (size_t)(blockIdx.y * BM) * DIM;
    const float* Bg = W + blockIdx.x * BN;

    float c[4][8][4];
#pragma unroll
    for (int mt = 0; mt < 4; mt++)
#pragma unroll
        for (int nt = 0; nt < 8; nt++)
#pragma unroll
            for (int i = 0; i < 4; i++) c[mt][nt][i] = 0.f;

    // prologue: stages 0..2 in flight
#pragma unroll
    for (int s = 0; s < 3; s++) { gemm_issue(As, Bs, s, Ag, Bg, tid); CP_COMMIT(); }

    for (int kt = 0; kt < NKT; kt++) {
        CP_WAIT2();
        __syncthreads();
        if (kt + 3 < NKT) gemm_issue(As, Bs, kt + 3, Ag, Bg, tid);
        CP_COMMIT();

        const int buf = kt & 3;
        const float* Ab = As + buf * ASTAGE;
        const float* Bb = Bs + buf * BSTAGE;
#pragma unroll
        for (int kk = 0; kk < BK; kk += 8) {
            unsigned a[4][4], b[8][2];
#pragma unroll
            for (int mt = 0; mt < 4; mt++) {
                int r0 = wm + mt * 16 + g;
                a[mt][0] = __float_as_uint(Ab[r0 * AST + kk + t]);
                a[mt][1] = __float_as_uint(Ab[(r0 + 8) * AST + kk + t]);
                a[mt][2] = __float_as_uint(Ab[r0 * AST + kk + t + 4]);
                a[mt][3] = __float_as_uint(Ab[(r0 + 8) * AST + kk + t + 4]);
            }
#pragma unroll
            for (int nt = 0; nt < 8; nt++) {
                int cc = wn + nt * 8 + g;
                b[nt][0] = __float_as_uint(Bb[(kk + t) * BST + cc]);
                b[nt][1] = __float_as_uint(Bb[(kk + t + 4) * BST + cc]);
            }
#pragma unroll
            for (int mt = 0; mt < 4; mt++)
#pragma unroll
                for (int nt = 0; nt < 8; nt++)
                    mma_tf32(c[mt][nt], a[mt], b[nt]);
        }
    }

    // epilogue
    const int rowB = blockIdx.y * BM + wm;
    const int colB = blockIdx.x * BN + wn;
#pragma unroll
    for (int mt = 0; mt < 4; mt++) {
        int r0 = rowB + mt * 16 + g;
#pragma unroll
        for (int nt = 0; nt < 8; nt++) {
            int col = colB + nt * 8 + 2 * t;
            float b0 = bias[col], b1 = bias[col + 1];
            float2 v;
            v.x = c[mt][nt][0] + b0; v.y = c[mt][nt][1] + b1;
            *(float2*)(C + (size_t)r0 * DIM + col) = v;
            v.x = c[mt][nt][2] + b0; v.y = c[mt][nt][3] + b1;
            *(float2*)(C + (size_t)(r0 + 8) * DIM + col) = v;
        }
    }
}

// Fused QKV variant: blockIdx.z selects (W, bias, out)
__global__ __launch_bounds__(256, 1)
void gemm_qkv_kernel(const float* __restrict__ A,
                     const float* __restrict__ Wq, const float* __restrict__ bq,
                     const float* __restrict__ Wk, const float* __restrict__ bk,
                     const float* __restrict__ Wv, const float* __restrict__ bv,
                     float* __restrict__ Cq, float* __restrict__ Ck,
                     float* __restrict__ Cv) {
    extern __shared__ float gsm[];
    float* As = gsm;
    float* Bs = gsm + 4 * ASTAGE;

    const float* W; const float* bias; float* C;
    if (blockIdx.z == 0)      { W = Wq; bias = bq; C = Cq; }
    else if (blockIdx.z == 1) { W = Wk; bias = bk; C = Ck; }
    else                      { W = Wv; bias = bv; C = Cv; }

    const int tid = threadIdx.x;
    const int lane = tid & 31, wid = tid >> 5;
    const int wm = (wid & 1) * 64;
    const int wn = (wid >> 1) * 64;
    const int g = lane >> 2, t = lane & 3;

    const float* Ag = A + (size_t)(blockIdx.y * BM) * DIM;
    const float* Bg = W + blockIdx.x * BN;

    float c[4][8][4];
#pragma unroll
    for (int mt = 0; mt < 4; mt++)
#pragma unroll
        for (int nt = 0; nt < 8; nt++)
#pragma unroll
            for (int i = 0; i < 4; i++) c[mt][nt][i] = 0.f;

#pragma unroll
    for (int s = 0; s < 3; s++) { gemm_issue(As, Bs, s, Ag, Bg, tid); CP_COMMIT(); }

    for (int kt = 0; kt < NKT; kt++) {
        CP_WAIT2();
        __syncthreads();
        if (kt + 3 < NKT) gemm_issue(As, Bs, kt + 3, Ag, Bg, tid);
        CP_COMMIT();

        const int buf = kt & 3;
        const float* Ab = As + buf * ASTAGE;
        const float* Bb = Bs + buf * BSTAGE;
#pragma unroll
        for (int kk = 0; kk < BK; kk += 8) {
            unsigned a[4][4], b[8][2];
#pragma unroll
            for (int mt = 0; mt < 4; mt++) {
                int r0 = wm + mt * 16 + g;
                a[mt][0] = __float_as_uint(Ab[r0 * AST + kk + t]);
                a[mt][1] = __float_as_uint(Ab[(r0 + 8) * AST + kk + t]);
                a[mt][2] = __float_as_uint(Ab[r0 * AST + kk + t + 4]);
                a[mt][3] = __float_as_uint(Ab[(r0 + 8) * AST + kk + t + 4]);
            }
#pragma unroll
            for (int nt = 0; nt < 8; nt++) {
                int cc = wn + nt * 8 + g;
                b[nt][0] = __float_as_uint(Bb[(kk + t) * BST + cc]);
                b[nt][1] = __float_as_uint(Bb[(kk + t + 4) * BST + cc]);
            }
#pragma unroll
            for (int mt = 0; mt < 4; mt++)
#pragma unroll
                for (int nt = 0; nt < 8; nt++)
                    mma_tf32(c[mt][nt], a[mt], b[nt]);
        }
    }

    const int rowB = blockIdx.y * BM + wm;
    const int colB = blockIdx.x * BN + wn;
#pragma unroll
    for (int mt = 0; mt < 4; mt++) {
        int r0 = rowB + mt * 16 + g;
#pragma unroll
        for (int nt = 0; nt < 8; nt++) {
            int col = colB + nt * 8 + 2 * t;
            float b0 = bias[col], b1 = bias[col + 1];
            float2 v;
            v.x = c[mt][nt][0] + b0; v.y = c[mt][nt][1] + b1;
            *(float2*)(C + (size_t)r0 * DIM + col) = v;
            v.x = c[mt][nt][2] + b0; v.y = c[mt][nt][3] + b1;
            *(float2*)(C + (size_t)(r0 + 8) * DIM + col) = v;
        }
    }
}

// ---------------------------------------------------------------------------
// RMSNorm + RoPE (unchanged)
// ---------------------------------------------------------------------------
__global__ __launch_bounds__(256)
void rmsnorm_rope_kernel(const float* __restrict__ fc, const float* __restrict__ fs,
                         const float* __restrict__ gq, const float* __restrict__ gk) {
    const int s = blockIdx.x;
    const int tid = threadIdx.x;
    float* qrow = g_q + (size_t)s * DIM;
    float* krow = g_k + (size_t)s * DIM;

    float q1[4], q2[4], k1[4], k2[4];
    float sq = 0.f, sk = 0.f;
#pragma unroll
    for (int j = 0; j < 4; j++) {
        int p = tid + j * 256;
        int h = p >> 6, jj = p & 63;
        int i1 = h * DH + 2 * jj;
        float2 qv = *(const float2*)(qrow + i1);
        float2 kv = *(const float2*)(krow + i1);
        q1[j] = qv.x; q2[j] = qv.y; k1[j] = kv.x; k2[j] = kv.y;
        sq += qv.x * qv.x + qv.y * qv.y;
        sk += kv.x * kv.x + kv.y * kv.y;
    }
#pragma unroll
    for (int off = 16; off > 0; off >>= 1) {
        sq += __shfl_xor_sync(0xffffffffu, sq, off);
        sk += __shfl_xor_sync(0xffffffffu, sk, off);
    }
    __shared__ float sh[16];
    if ((tid & 31) == 0) { sh[tid >> 5] = sq; sh[8 + (tid >> 5)] = sk; }
    __syncthreads();
    float tq = 0.f, tk = 0.f;
#pragma unroll
    for (int w = 0; w < 8; w++) { tq += sh[w]; tk += sh[8 + w]; }
    const float rq = rsqrtf(tq * (1.0f / DIM) + 1e-5f);
    const float rk = rsqrtf(tk * (1.0f / DIM) + 1e-5f);

#pragma unroll
    for (int j = 0; j < 4; j++) {
        int p = tid + j * 256;
        int h = p >> 6, jj = p & 63;
        int i1 = h * DH + 2 * jj;
        float c = fc[(size_t)s * DH + 2 * jj];
        float sn = fs[(size_t)s * DH + 2 * jj + 1];
        float x1 = q1[j] * rq * gq[i1];
        float x2 = q2[j] * rq * gq[i1 + 1];
        float2 oq; oq.x = x1 * c - x2 * sn; oq.y = x1 * sn + x2 * c;
        *(float2*)(qrow + i1) = oq;
        x1 = k1[j] * rk * gk[i1];
        x2 = k2[j] * rk * gk[i1 + 1];
        float2 ok; ok.x = x1 * c - x2 * sn; ok.y = x1 * sn + x2 * c;
        *(float2*)(krow + i1) = ok;
    }
}

// ---------------------------------------------------------------------------
// Flash attention, tf32 tensor-core (unchanged — passing @ ~360us)
// ---------------------------------------------------------------------------
#define BQ 128
#define BKV 64
#define QS 132
#define KS 132
#define VS 136
#define PS 68
#define ATTN_SMEM ((BQ * QS + BKV * KS + BKV * VS + BQ * PS) * 4)

__global__ __launch_bounds__(256, 1)
void attn_kernel() {
    extern __shared__ unsigned smu[];
    unsigned* Qs = smu;
    unsigned* Ks = Qs + BQ * QS;
    unsigned* Vs = Ks + BKV * KS;
    unsigned* Ps = Vs + BKV * VS;

    const int h = blockIdx.y;
    const int q0 = blockIdx.x * BQ;
    const int tid = threadIdx.x;
    const int lane = tid & 31, wid = tid >> 5;
    const int g = lane >> 2, t = lane & 3;
    const int rbase = wid * 16;
    const float scale = 0.08838834764831845f;

#pragma unroll
    for (int i = 0; i < 16; i++) {
        int idx = tid + i * 256;
        int r = idx >> 5, c4 = (idx & 31) * 4;
        float4 v = *(const float4*)(g_q + (size_t)(q0 + r) * DIM + h * DH + c4);
        unsigned* dst = Qs + r * QS + c4;
        dst[0] = tf32r(v.x * scale); dst[1] = tf32r(v.y * scale);
        dst[2] = tf32r(v.z * scale); dst[3] = tf32r(v.w * scale);
    }

    float o[16][4];
#pragma unroll
    for (int nt = 0; nt < 16; nt++)
#pragma unroll
        for (int i = 0; i < 4; i++) o[nt][i] = 0.f;
    float m0 = -1e30f, m1 = -1e30f, l0 = 0.f, l1 = 0.f;

    for (int kt = 0; kt < SEQ / BKV; kt++) {
        __syncthreads();
        const int tok0 = kt * BKV;
#pragma unroll
        for (int i = 0; i < 8; i++) {
            int idx = tid + i * 256;
            int r = idx >> 5, c4 = (idx & 31) * 4;
            float4 kv = *(const float4*)(g_k + (size_t)(tok0 + r) * DIM + h * DH + c4);
            unsigned* kd = Ks + r * KS + c4;
            kd[0] = tf32r(kv.x); kd[1] = tf32r(kv.y); kd[2] = tf32r(kv.z); kd[3] = tf32r(kv.w);
            float4 vv = *(const float4*)(g_v + (size_t)(tok0 + r) * DIM + h * DH + c4);
            unsigned* vd = Vs + r * VS + c4;
            vd[0] = tf32r(vv.x); vd[1] = tf32r(vv.y); vd[2] = tf32r(vv.z); vd[3] = tf32r(vv.w);
        }
        __syncthreads();

        float s[8][4];
#pragma unroll
        for (int nt = 0; nt < 8; nt++)
#pragma unroll
            for (int i = 0; i < 4; i++) s[nt][i] = 0.f;

#pragma unroll
        for (int kk = 0; kk < DH; kk += 8) {
            unsigned a[4];
            a[0] = Qs[(rbase + g) * QS + kk + t];
            a[1] = Qs[(rbase + g + 8) * QS + kk + t];
            a[2] = Qs[(rbase + g) * QS + kk + t + 4];
            a[3] = Qs[(rbase + g + 8) * QS + kk + t + 4];
#pragma unroll
            for (int nt = 0; nt < 8; nt++) {
                unsigned b[2];
                b[0] = Ks[(nt * 8 + g) * KS + kk + t];
                b[1] = Ks[(nt * 8 + g) * KS + kk + t + 4];
                mma_tf32(s[nt], a, b);
            }
        }

        float mx0 = -1e30f, mx1 = -1e30f;
#pragma unroll
        for (int nt = 0; nt < 8; nt++) {
            mx0 = fmaxf(mx0, fmaxf(s[nt][0], s[nt][1]));
            mx1 = fmaxf(mx1, fmaxf(s[nt][2], s[nt][3]));
        }
        mx0 = fmaxf(mx0, __shfl_xor_sync(0xffffffffu, mx0, 1));
        mx0 = fmaxf(mx0, __shfl_xor_sync(0xffffffffu, mx0, 2));
        mx1 = fmaxf(mx1, __shfl_xor_sync(0xffffffffu, mx1, 1));
        mx1 = fmaxf(mx1, __shfl_xor_sync(0xffffffffu, mx1, 2));

        float mn0 = fmaxf(m0, mx0), mn1 = fmaxf(m1, mx1);
        float al0 = __expf(m0 - mn0), al1 = __expf(m1 - mn1);
        float sum0 = 0.f, sum1 = 0.f;
#pragma unroll
        for (int nt = 0; nt < 8; nt++) {
            float p00 = __expf(s[nt][0] - mn0);
            float p01 = __expf(s[nt][1] - mn0);
            float p10 = __expf(s[nt][2] - mn1);
            float p11 = __expf(s[nt][3] - mn1);
            sum0 += p00 + p01; sum1 += p10 + p11;
            uint2 u0; u0.x = tf32r(p00); u0.y = tf32r(p01);
            *(uint2*)&Ps[(rbase + g) * PS + nt * 8 + 2 * t] = u0;
            uint2 u1; u1.x = tf32r(p10); u1.y = tf32r(p11);
            *(uint2*)&Ps[(rbase + g + 8) * PS + nt * 8 + 2 * t] = u1;
        }
        sum0 += __shfl_xor_sync(0xffffffffu, sum0, 1);
        sum0 += __shfl_xor_sync(0xffffffffu, sum0, 2);
        sum1 += __shfl_xor_sync(0xffffffffu, sum1, 1);
        sum1 += __shfl_xor_sync(0xffffffffu, sum1, 2);
        l0 = l0 * al0 + sum0; l1 = l1 * al1 + sum1;
        m0 = mn0; m1 = mn1;
#pragma unroll
        for (int nt = 0; nt < 16; nt++) {
            o[nt][0] *= al0; o[nt][1] *= al0;
            o[nt][2] *= al1; o[nt][3] *= al1;
        }
        __syncwarp();

#pragma unroll
        for (int kk = 0; kk < BKV; kk += 8) {
            unsigned a[4];
            a[0] = Ps[(rbase + g) * PS + kk + t];
            a[1] = Ps[(rbase + g + 8) * PS + kk + t];
            a[2] = Ps[(rbase + g) * PS + kk + t + 4];
            a[3] = Ps[(rbase + g + 8) * PS + kk + t + 4];
#pragma unroll
            for (int nt = 0; nt < 16; nt++) {
                unsigned b[2];
                b[0] = Vs[(kk + t) * VS + nt * 8 + g];
                b[1] = Vs[(kk + t + 4) * VS + nt * 8 + g];
                mma_tf32(o[nt], a, b);
            }
        }
    }

    const float inv0 = 1.0f / l0, inv1 = 1.0f / l1;
    const int r0 = q0 + rbase + g, r1 = r0 + 8;
#pragma unroll
    for (int nt = 0; nt < 16; nt++) {
        int col = h * DH + nt * 8 + 2 * t;
        float2 w0; w0.x = o[nt][0] * inv0; w0.y = o[nt][1] * inv0;
        *(float2*)(g_att + (size_t)r0 * DIM + col) = w0;
        float2 w1; w1.x = o[nt][2] * inv1; w1.y = o[nt][3] * inv1;
        *(float2*)(g_att + (size_t)r1 * DIM + col) = w1;
    }
}

// ---------------------------------------------------------------------------
// Host launch
// ---------------------------------------------------------------------------
extern "C" void kernel_launch(void* const* d_in, const int* in_sizes, int n_in,
                              void* d_out, int out_size) {
    const float* x  = (const float*)d_in[0];
    const float* fc = (const float*)d_in[1];
    const float* fs = (const float*)d_in[2];
    const float* Wq = (const float*)d_in[3];
    const float* bq = (const float*)d_in[4];
    const float* Wk = (const float*)d_in[5];
    const float* bk = (const float*)d_in[6];
    const float* Wv = (const float*)d_in[7];
    const float* bv = (const float*)d_in[8];
    const float* Wo = (const float*)d_in[9];
    const float* bo = (const float*)d_in[10];
    const float* gq = (const float*)d_in[11];
    const float* gk = (const float*)d_in[12];
    float* out = (float*)d_out;

    float *q, *k, *v, *att;
    cudaGetSymbolAddress((void**)&q,   g_q);
    cudaGetSymbolAddress((void**)&k,   g_k);
    cudaGetSymbolAddress((void**)&v,   g_v);
    cudaGetSymbolAddress((void**)&att, g_att);

    cudaFuncSetAttribute(gemm_qkv_kernel, cudaFuncAttributeMaxDynamicSharedMemorySize,
                         GEMM_SMEM);
    cudaFuncSetAttribute(gemm_bias_kernel, cudaFuncAttributeMaxDynamicSharedMemorySize,
                         GEMM_SMEM);
    cudaFuncSetAttribute(attn_kernel, cudaFuncAttributeMaxDynamicSharedMemorySize,
                         ATTN_SMEM);

    dim3 qkv_grid(DIM / BN, SEQ / BM, 3);
    gemm_qkv_kernel<<<qkv_grid, 256, GEMM_SMEM>>>(x, Wq, bq, Wk, bk, Wv, bv, q, k, v);
    rmsnorm_rope_kernel<<<SEQ, 256>>>(fc, fs, gq, gk);
    attn_kernel<<<dim3(SEQ / BQ, NH), 256, ATTN_SMEM>>>();
    dim3 gemm_grid(DIM / BN, SEQ / BM);
    gemm_bias_kernel<<<gemm_grid, 256, GEMM_SMEM>>>(att, Wo, bo, out);
}

// round 6
// speedup vs baseline: 4.6209x; 1.0457x over previous
#include <cuda_runtime.h>
#include <math.h>

#define SEQ 4096
#define DIM 2048
#define NH 16
#define DH 128

// Scratch (static device arrays — no allocations allowed)
__device__ float g_q[SEQ * DIM];
__device__ float g_k[SEQ * DIM];
__device__ float g_v[SEQ * DIM];
__device__ float g_att[SEQ * DIM];
__device__ float g_xt[SEQ * DIM];        // tf32-rounded hidden_states
__device__ float g_w[4 * DIM * DIM];     // tf32-rounded Wq,Wk,Wv,Wo

__device__ __forceinline__ unsigned tf32r(float f) {
    unsigned u;
    asm("cvt.rna.tf32.f32 %0, %1;" : "=r"(u) : "f"(f));
    return u;
}
__device__ __forceinline__ float tf32rf(float f) { return __uint_as_float(tf32r(f)); }

__device__ __forceinline__ void mma_tf32(float* c, const unsigned* a, const unsigned* b) {
    asm volatile(
        "mma.sync.aligned.m16n8k8.row.col.f32.tf32.tf32.f32 "
        "{%0,%1,%2,%3}, {%4,%5,%6,%7}, {%8,%9}, {%0,%1,%2,%3};\n"
        : "+f"(c[0]), "+f"(c[1]), "+f"(c[2]), "+f"(c[3])
        : "r"(a[0]), "r"(a[1]), "r"(a[2]), "r"(a[3]), "r"(b[0]), "r"(b[1]));
}

__device__ __forceinline__ void cpa16(void* dst, const void* src) {
    unsigned d = (unsigned)__cvta_generic_to_shared(dst);
    asm volatile("cp.async.cg.shared.global [%0], [%1], 16;\n" :: "r"(d), "l"(src));
}
#define CP_COMMIT() asm volatile("cp.async.commit_group;\n" ::: "memory")
#define CP_WAIT2()  asm volatile("cp.async.wait_group 2;\n" ::: "memory")
#define CP_WAIT0()  asm volatile("cp.async.wait_group 0;\n" ::: "memory")

// ---------------------------------------------------------------------------
// Pre-round tensors to the tf32 grid (producer-side rounding)
// ---------------------------------------------------------------------------
__global__ void roundcvt_kernel(const float* __restrict__ s, float* __restrict__ d, int n4) {
    int i = blockIdx.x * blockDim.x + threadIdx.x;
    int stride = gridDim.x * blockDim.x;
    for (; i < n4; i += stride) {
        float4 v = ((const float4*)s)[i];
        v.x = tf32rf(v.x); v.y = tf32rf(v.y); v.z = tf32rf(v.z); v.w = tf32rf(v.w);
        ((float4*)d)[i] = v;
    }
}

// ---------------------------------------------------------------------------
// tf32 GEMM, 4-stage cp.async pipeline. Inputs pre-rounded -> raw-bit feed.
// Block 128x256, BK=16, 8 warps (64x64 each).
// ---------------------------------------------------------------------------
#define BM 128
#define BN 256
#define BK 16
#define AST 20
#define BST 264
#define ASTAGE (BM * AST)
#define BSTAGE (BK * BST)
#define GEMM_SMEM ((4 * ASTAGE + 4 * BSTAGE) * 4)
#define NKT (DIM / BK)

__device__ __forceinline__ void gemm_issue(float* As, float* Bs, int kt,
                                           const float* Ag, const float* Bg, int tid) {
    const int stg = kt & 3;
    const int k0 = kt * BK;
    float* Ad = As + stg * ASTAGE;
    float* Bd = Bs + stg * BSTAGE;
#pragma unroll
    for (int i = 0; i < 2; i++) {
        int idx = tid + i * 256;
        int r = idx >> 2, c = (idx & 3) * 4;
        cpa16(Ad + r * AST + c, Ag + (size_t)r * DIM + k0 + c);
    }
#pragma unroll
    for (int i = 0; i < 4; i++) {
        int idx = tid + i * 256;
        int r = idx >> 6, c = (idx & 63) * 4;
        cpa16(Bd + r * BST + c, Bg + (size_t)(k0 + r) * DIM + c);
    }
}

// ROUND_OUT: 1 -> round outputs to tf32 grid (feeds later tensor stages)
template <int ROUND_OUT>
__device__ __forceinline__ void gemm_body(const float* Ag, const float* Bg,
                                          const float* bias, float* C,
                                          float* As, float* Bs,
                                          int bx, int by, int tid) {
    const int lane = tid & 31, wid = tid >> 5;
    const int wm = (wid & 1) * 64;
    const int wn = (wid >> 1) * 64;
    const int g = lane >> 2, t = lane & 3;

    float c[4][8][4];
#pragma unroll
    for (int mt = 0; mt < 4; mt++)
#pragma unroll
        for (int nt = 0; nt < 8; nt++)
#pragma unroll
            for (int i = 0; i < 4; i++) c[mt][nt][i] = 0.f;

#pragma unroll
    for (int s = 0; s < 3; s++) { gemm_issue(As, Bs, s, Ag, Bg, tid); CP_COMMIT(); }

    for (int kt = 0; kt < NKT; kt++) {
        CP_WAIT2();
        __syncthreads();
        if (kt + 3 < NKT) gemm_issue(As, Bs, kt + 3, Ag, Bg, tid);
        CP_COMMIT();

        const int buf = kt & 3;
        const float* Ab = As + buf * ASTAGE;
        const float* Bb = Bs + buf * BSTAGE;
#pragma unroll
        for (int kk = 0; kk < BK; kk += 8) {
            unsigned a[4][4], b[8][2];
#pragma unroll
            for (int mt = 0; mt < 4; mt++) {
                int r0 = wm + mt * 16 + g;
                a[mt][0] = __float_as_uint(Ab[r0 * AST + kk + t]);
                a[mt][1] = __float_as_uint(Ab[(r0 + 8) * AST + kk + t]);
                a[mt][2] = __float_as_uint(Ab[r0 * AST + kk + t + 4]);
                a[mt][3] = __float_as_uint(Ab[(r0 + 8) * AST + kk + t + 4]);
            }
#pragma unroll
            for (int nt = 0; nt < 8; nt++) {
                int cc = wn + nt * 8 + g;
                b[nt][0] = __float_as_uint(Bb[(kk + t) * BST + cc]);
                b[nt][1] = __float_as_uint(Bb[(kk + t + 4) * BST + cc]);
            }
#pragma unroll
            for (int mt = 0; mt < 4; mt++)
#pragma unroll
                for (int nt = 0; nt < 8; nt++)
                    mma_tf32(c[mt][nt], a[mt], b[nt]);
        }
    }

    const int rowB = by * BM + wm;
    const int colB = bx * BN + wn;
#pragma unroll
    for (int mt = 0; mt < 4; mt++) {
        int r0 = rowB + mt * 16 + g;
#pragma unroll
        for (int nt = 0; nt < 8; nt++) {
            int col = colB + nt * 8 + 2 * t;
            float b0 = bias[col], b1 = bias[col + 1];
            float2 v;
            if (ROUND_OUT) {
                v.x = tf32rf(c[mt][nt][0] + b0); v.y = tf32rf(c[mt][nt][1] + b1);
                *(float2*)(C + (size_t)r0 * DIM + col) = v;
                v.x = tf32rf(c[mt][nt][2] + b0); v.y = tf32rf(c[mt][nt][3] + b1);
                *(float2*)(C + (size_t)(r0 + 8) * DIM + col) = v;
            } else {
                v.x = c[mt][nt][0] + b0; v.y = c[mt][nt][1] + b1;
                *(float2*)(C + (size_t)r0 * DIM + col) = v;
                v.x = c[mt][nt][2] + b0; v.y = c[mt][nt][3] + b1;
                *(float2*)(C + (size_t)(r0 + 8) * DIM + col) = v;
            }
        }
    }
}

__global__ __launch_bounds__(256, 1)
void gemm_proj_kernel(const float* __restrict__ A, const float* __restrict__ W,
                      const float* __restrict__ bias, float* __restrict__ C) {
    extern __shared__ float gsm[];
    gemm_body<0>(A + (size_t)(blockIdx.y * BM) * DIM, W + blockIdx.x * BN,
                 bias, C, gsm, gsm + 4 * ASTAGE, blockIdx.x, blockIdx.y, threadIdx.x);
}

__global__ __launch_bounds__(256, 1)
void gemm_qkv_kernel(const float* __restrict__ A, const float* __restrict__ Wall,
                     const float* __restrict__ bq, const float* __restrict__ bk,
                     const float* __restrict__ bv,
                     float* __restrict__ Cq, float* __restrict__ Ck,
                     float* __restrict__ Cv) {
    extern __shared__ float gsm[];
    const float* bias; float* C;
    const float* W = Wall + (size_t)blockIdx.z * DIM * DIM;
    if (blockIdx.z == 0)      { bias = bq; C = Cq; }
    else if (blockIdx.z == 1) { bias = bk; C = Ck; }
    else                      { bias = bv; C = Cv; }
    gemm_body<1>(A + (size_t)(blockIdx.y * BM) * DIM, W + blockIdx.x * BN,
                 bias, C, gsm, gsm + 4 * ASTAGE, blockIdx.x, blockIdx.y, threadIdx.x);
}

// ---------------------------------------------------------------------------
// RMSNorm + RoPE — outputs rounded to tf32 grid
// ---------------------------------------------------------------------------
__global__ __launch_bounds__(256)
void rmsnorm_rope_kernel(const float* __restrict__ fc, const float* __restrict__ fs,
                         const float* __restrict__ gq, const float* __restrict__ gk) {
    const int s = blockIdx.x;
    const int tid = threadIdx.x;
    float* qrow = g_q + (size_t)s * DIM;
    float* krow = g_k + (size_t)s * DIM;

    float q1[4], q2[4], k1[4], k2[4];
    float sq = 0.f, sk = 0.f;
#pragma unroll
    for (int j = 0; j < 4; j++) {
        int p = tid + j * 256;
        int h = p >> 6, jj = p & 63;
        int i1 = h * DH + 2 * jj;
        float2 qv = *(const float2*)(qrow + i1);
        float2 kv = *(const float2*)(krow + i1);
        q1[j] = qv.x; q2[j] = qv.y; k1[j] = kv.x; k2[j] = kv.y;
        sq += qv.x * qv.x + qv.y * qv.y;
        sk += kv.x * kv.x + kv.y * kv.y;
    }
#pragma unroll
    for (int off = 16; off > 0; off >>= 1) {
        sq += __shfl_xor_sync(0xffffffffu, sq, off);
        sk += __shfl_xor_sync(0xffffffffu, sk, off);
    }
    __shared__ float sh[16];
    if ((tid & 31) == 0) { sh[tid >> 5] = sq; sh[8 + (tid >> 5)] = sk; }
    __syncthreads();
    float tq = 0.f, tk = 0.f;
#pragma unroll
    for (int w = 0; w < 8; w++) { tq += sh[w]; tk += sh[8 + w]; }
    const float rq = rsqrtf(tq * (1.0f / DIM) + 1e-5f);
    const float rk = rsqrtf(tk * (1.0f / DIM) + 1e-5f);

#pragma unroll
    for (int j = 0; j < 4; j++) {
        int p = tid + j * 256;
        int h = p >> 6, jj = p & 63;
        int i1 = h * DH + 2 * jj;
        float c = fc[(size_t)s * DH + 2 * jj];
        float sn = fs[(size_t)s * DH + 2 * jj + 1];
        float x1 = q1[j] * rq * gq[i1];
        float x2 = q2[j] * rq * gq[i1 + 1];
        float2 oq; oq.x = tf32rf(x1 * c - x2 * sn); oq.y = tf32rf(x1 * sn + x2 * c);
        *(float2*)(qrow + i1) = oq;
        x1 = k1[j] * rk * gk[i1];
        x2 = k2[j] * rk * gk[i1 + 1];
        float2 ok; ok.x = tf32rf(x1 * c - x2 * sn); ok.y = tf32rf(x1 * sn + x2 * c);
        *(float2*)(krow + i1) = ok;
    }
}

// ---------------------------------------------------------------------------
// Flash attention, tf32 MMA, cp.async K (double-buffered) + V (single).
// K/V arrive raw (already tf32-rounded upstream) — never touch the RF.
// ---------------------------------------------------------------------------
#define BQ 128
#define BKV 64
#define QS 132
#define KS 132
#define VS 136
#define PS 68
#define KSTG (BKV * KS)
#define ATTN_SMEM ((BQ * QS + 2 * KSTG + BKV * VS + BQ * PS) * 4)
#define NT (SEQ / BKV)

__global__ __launch_bounds__(256, 1)
void attn_kernel() {
    extern __shared__ unsigned smu[];
    unsigned* Qs = smu;
    unsigned* K0 = Qs + BQ * QS;
    unsigned* Vs = K0 + 2 * KSTG;
    unsigned* Ps = Vs + BKV * VS;

    const int h = blockIdx.y;
    const int q0 = blockIdx.x * BQ;
    const int tid = threadIdx.x;
    const int lane = tid & 31, wid = tid >> 5;
    const int g = lane >> 2, t = lane & 3;
    const int rbase = wid * 16;
    const float scale = 0.08838834764831845f;   // 1/sqrt(128)

    // stage Q (pre-scaled + rounded)
#pragma unroll
    for (int i = 0; i < 16; i++) {
        int idx = tid + i * 256;
        int r = idx >> 5, c4 = (idx & 31) * 4;
        float4 v = *(const float4*)(g_q + (size_t)(q0 + r) * DIM + h * DH + c4);
        unsigned* dst = Qs + r * QS + c4;
        dst[0] = tf32r(v.x * scale); dst[1] = tf32r(v.y * scale);
        dst[2] = tf32r(v.z * scale); dst[3] = tf32r(v.w * scale);
    }

    // prologue: K(0) -> buf0
#pragma unroll
    for (int i = 0; i < 8; i++) {
        int idx = tid + i * 256;
        int r = idx >> 5, c4 = (idx & 31) * 4;
        cpa16(K0 + r * KS + c4, g_k + (size_t)r * DIM + h * DH + c4);
    }
    CP_COMMIT();

    float o[16][4];
#pragma unroll
    for (int nt = 0; nt < 16; nt++)
#pragma unroll
        for (int i = 0; i < 4; i++) o[nt][i] = 0.f;
    float m0 = -1e30f, m1 = -1e30f, l0 = 0.f, l1 = 0.f;

    for (int kt = 0; kt < NT; kt++) {
        if (kt == 0) CP_WAIT0();
        __syncthreads();      // K(kt) visible; prior PV done with Vs/Ps
        const int tok0 = kt * BKV;

        // issue V(kt) and K(kt+1)
#pragma unroll
        for (int i = 0; i < 8; i++) {
            int idx = tid + i * 256;
            int r = idx >> 5, c4 = (idx & 31) * 4;
            cpa16(Vs + r * VS + c4, g_v + (size_t)(tok0 + r) * DIM + h * DH + c4);
        }
        CP_COMMIT();
        if (kt + 1 < NT) {
            unsigned* Kn = K0 + ((kt + 1) & 1) * KSTG;
#pragma unroll
            for (int i = 0; i < 8; i++) {
                int idx = tid + i * 256;
                int r = idx >> 5, c4 = (idx & 31) * 4;
                cpa16(Kn + r * KS + c4, g_k + (size_t)(tok0 + BKV + r) * DIM + h * DH + c4);
            }
            CP_COMMIT();
        }

        const unsigned* Kb = K0 + (kt & 1) * KSTG;

        // ---- S = Q K^T (16x64 per warp) ----
        float s[8][4];
#pragma unroll
        for (int nt = 0; nt < 8; nt++)
#pragma unroll
            for (int i = 0; i < 4; i++) s[nt][i] = 0.f;

#pragma unroll
        for (int kk = 0; kk < DH; kk += 8) {
            unsigned a[4];
            a[0] = Qs[(rbase + g) * QS + kk + t];
            a[1] = Qs[(rbase + g + 8) * QS + kk + t];
            a[2] = Qs[(rbase + g) * QS + kk + t + 4];
            a[3] = Qs[(rbase + g + 8) * QS + kk + t + 4];
#pragma unroll
            for (int nt = 0; nt < 8; nt++) {
                unsigned b[2];
                b[0] = Kb[(nt * 8 + g) * KS + kk + t];
                b[1] = Kb[(nt * 8 + g) * KS + kk + t + 4];
                mma_tf32(s[nt], a, b);
            }
        }

        // ---- online softmax ----
        float mx0 = -1e30f, mx1 = -1e30f;
#pragma unroll
        for (int nt = 0; nt < 8; nt++) {
            mx0 = fmaxf(mx0, fmaxf(s[nt][0], s[nt][1]));
            mx1 = fmaxf(mx1, fmaxf(s[nt][2], s[nt][3]));
        }
        mx0 = fmaxf(mx0, __shfl_xor_sync(0xffffffffu, mx0, 1));
        mx0 = fmaxf(mx0, __shfl_xor_sync(0xffffffffu, mx0, 2));
        mx1 = fmaxf(mx1, __shfl_xor_sync(0xffffffffu, mx1, 1));
        mx1 = fmaxf(mx1, __shfl_xor_sync(0xffffffffu, mx1, 2));

        float mn0 = fmaxf(m0, mx0), mn1 = fmaxf(m1, mx1);
        float al0 = __expf(m0 - mn0), al1 = __expf(m1 - mn1);
        float sum0 = 0.f, sum1 = 0.f;
#pragma unroll
        for (int nt = 0; nt < 8; nt++) {
            float p00 = __expf(s[nt][0] - mn0);
            float p01 = __expf(s[nt][1] - mn0);
            float p10 = __expf(s[nt][2] - mn1);
            float p11 = __expf(s[nt][3] - mn1);
            sum0 += p00 + p01; sum1 += p10 + p11;
            uint2 u0; u0.x = tf32r(p00); u0.y = tf32r(p01);
            *(uint2*)&Ps[(rbase + g) * PS + nt * 8 + 2 * t] = u0;
            uint2 u1; u1.x = tf32r(p10); u1.y = tf32r(p11);
            *(uint2*)&Ps[(rbase + g + 8) * PS + nt * 8 + 2 * t] = u1;
        }
        sum0 += __shfl_xor_sync(0xffffffffu, sum0, 1);
        sum0 += __shfl_xor_sync(0xffffffffu, sum0, 2);
        sum1 += __shfl_xor_sync(0xffffffffu, sum1, 1);
        sum1 += __shfl_xor_sync(0xffffffffu, sum1, 2);
        l0 = l0 * al0 + sum0; l1 = l1 * al1 + sum1;
        m0 = mn0; m1 = mn1;
#pragma unroll
        for (int nt = 0; nt < 16; nt++) {
            o[nt][0] *= al0; o[nt][1] *= al0;
            o[nt][2] *= al1; o[nt][3] *= al1;
        }

        CP_WAIT0();           // V(kt) (+ K(kt+1)) complete
        __syncthreads();      // V visible to all; P (same-warp) also ordered

        // ---- O += P V ----
#pragma unroll
        for (int kk = 0; kk < BKV; kk += 8) {
            unsigned a[4];
            a[0] = Ps[(rbase + g) * PS + kk + t];
            a[1] = Ps[(rbase + g + 8) * PS + kk + t];
            a[2] = Ps[(rbase + g) * PS + kk + t + 4];
            a[3] = Ps[(rbase + g + 8) * PS + kk + t + 4];
#pragma unroll
            for (int nt = 0; nt < 16; nt++) {
                unsigned b[2];
                b[0] = Vs[(kk + t) * VS + nt * 8 + g];
                b[1] = Vs[(kk + t + 4) * VS + nt * 8 + g];
                mma_tf32(o[nt], a, b);
            }
        }
    }

    // epilogue (rounded -> proj GEMM feeds raw bits)
    const float inv0 = 1.0f / l0, inv1 = 1.0f / l1;
    const int r0 = q0 + rbase + g, r1 = r0 + 8;
#pragma unroll
    for (int nt = 0; nt < 16; nt++) {
        int col = h * DH + nt * 8 + 2 * t;
        float2 w0; w0.x = tf32rf(o[nt][0] * inv0); w0.y = tf32rf(o[nt][1] * inv0);
        *(float2*)(g_att + (size_t)r0 * DIM + col) = w0;
        float2 w1; w1.x = tf32rf(o[nt][2] * inv1); w1.y = tf32rf(o[nt][3] * inv1);
        *(float2*)(g_att + (size_t)r1 * DIM + col) = w1;
    }
}

// ---------------------------------------------------------------------------
// Host launch
// ---------------------------------------------------------------------------
extern "C" void kernel_launch(void* const* d_in, const int* in_sizes, int n_in,
                              void* d_out, int out_size) {
    const float* x  = (const float*)d_in[0];
    const float* fc = (const float*)d_in[1];
    const float* fs = (const float*)d_in[2];
    const float* Wq = (const float*)d_in[3];
    const float* bq = (const float*)d_in[4];
    const float* Wk = (const float*)d_in[5];
    const float* bk = (const float*)d_in[6];
    const float* Wv = (const float*)d_in[7];
    const float* bv = (const float*)d_in[8];
    const float* Wo = (const float*)d_in[9];
    const float* bo = (const float*)d_in[10];
    const float* gq = (const float*)d_in[11];
    const float* gk = (const float*)d_in[12];
    float* out = (float*)d_out;

    float *q, *k, *v, *att, *xt, *w;
    cudaGetSymbolAddress((void**)&q,   g_q);
    cudaGetSymbolAddress((void**)&k,   g_k);
    cudaGetSymbolAddress((void**)&v,   g_v);
    cudaGetSymbolAddress((void**)&att, g_att);
    cudaGetSymbolAddress((void**)&xt,  g_xt);
    cudaGetSymbolAddress((void**)&w,   g_w);

    cudaFuncSetAttribute(gemm_qkv_kernel, cudaFuncAttributeMaxDynamicSharedMemorySize,
                         GEMM_SMEM);
    cudaFuncSetAttribute(gemm_proj_kernel, cudaFuncAttributeMaxDynamicSharedMemorySize,
                         GEMM_SMEM);
    cudaFuncSetAttribute(attn_kernel, cudaFuncAttributeMaxDynamicSharedMemorySize,
                         ATTN_SMEM);

    // producer-side rounding
    roundcvt_kernel<<<512, 256>>>(x,  xt,            SEQ * DIM / 4);
    roundcvt_kernel<<<512, 256>>>(Wq, w,             DIM * DIM / 4);
    roundcvt_kernel<<<512, 256>>>(Wk, w + (size_t)DIM * DIM,     DIM * DIM / 4);
    roundcvt_kernel<<<512, 256>>>(Wv, w + (size_t)2 * DIM * DIM, DIM * DIM / 4);
    roundcvt_kernel<<<512, 256>>>(Wo, w + (size_t)3 * DIM * DIM, DIM * DIM / 4);

    dim3 qkv_grid(DIM / BN, SEQ / BM, 3);
    gemm_qkv_kernel<<<qkv_grid, 256, GEMM_SMEM>>>(xt, w, bq, bk, bv, q, k, v);
    rmsnorm_rope_kernel<<<SEQ, 256>>>(fc, fs, gq, gk);
    attn_kernel<<<dim3(SEQ / BQ, NH), 256, ATTN_SMEM>>>();
    dim3 gemm_grid(DIM / BN, SEQ / BM);
    gemm_proj_kernel<<<gemm_grid, 256, GEMM_SMEM>>>(att, w + (size_t)3 * DIM * DIM,
                                                    bo, out);
}

// round 7
// speedup vs baseline: 4.8511x; 1.0498x over previous
#include <cuda_runtime.h>
#include <math.h>

#define SEQ 4096
#define DIM 2048
#define NH 16
#define DH 128

// Scratch (static device arrays — no allocations allowed)
__device__ float g_q[SEQ * DIM];
__device__ float g_k[SEQ * DIM];
__device__ float g_v[SEQ * DIM];
__device__ float g_att[SEQ * DIM];
__device__ float g_xt[SEQ * DIM];        // tf32-rounded hidden_states
__device__ float g_w[4 * DIM * DIM];     // tf32-rounded Wq,Wk,Wv,Wo

__device__ __forceinline__ unsigned tf32r(float f) {
    unsigned u;
    asm("cvt.rna.tf32.f32 %0, %1;" : "=r"(u) : "f"(f));
    return u;
}
__device__ __forceinline__ float tf32rf(float f) { return __uint_as_float(tf32r(f)); }

__device__ __forceinline__ void mma_tf32(float* c, const unsigned* a, const unsigned* b) {
    asm volatile(
        "mma.sync.aligned.m16n8k8.row.col.f32.tf32.tf32.f32 "
        "{%0,%1,%2,%3}, {%4,%5,%6,%7}, {%8,%9}, {%0,%1,%2,%3};\n"
        : "+f"(c[0]), "+f"(c[1]), "+f"(c[2]), "+f"(c[3])
        : "r"(a[0]), "r"(a[1]), "r"(a[2]), "r"(a[3]), "r"(b[0]), "r"(b[1]));
}

__device__ __forceinline__ void cpa16(void* dst, const void* src) {
    unsigned d = (unsigned)__cvta_generic_to_shared(dst);
    asm volatile("cp.async.cg.shared.global [%0], [%1], 16;\n" :: "r"(d), "l"(src));
}
#define CP_COMMIT() asm volatile("cp.async.commit_group;\n" ::: "memory")
#define CP_WAIT1()  asm volatile("cp.async.wait_group 1;\n" ::: "memory")
#define CP_WAIT0()  asm volatile("cp.async.wait_group 0;\n" ::: "memory")

// ---------------------------------------------------------------------------
// Pre-round tensors to tf32 grid — single launch, grid.z selects tensor
// ---------------------------------------------------------------------------
__global__ void roundcvt5_kernel(const float* __restrict__ x,
                                 const float* __restrict__ Wq,
                                 const float* __restrict__ Wk,
                                 const float* __restrict__ Wv,
                                 const float* __restrict__ Wo) {
    const float* s; float* d; int n4;
    const int wsz = DIM * DIM / 4;
    if (blockIdx.z == 0)      { s = x;  d = g_xt; n4 = SEQ * DIM / 4; }
    else if (blockIdx.z == 1) { s = Wq; d = g_w;                 n4 = wsz; }
    else if (blockIdx.z == 2) { s = Wk; d = g_w + (size_t)DIM * DIM;     n4 = wsz; }
    else if (blockIdx.z == 3) { s = Wv; d = g_w + (size_t)2 * DIM * DIM; n4 = wsz; }
    else                      { s = Wo; d = g_w + (size_t)3 * DIM * DIM; n4 = wsz; }
    int i = blockIdx.x * blockDim.x + threadIdx.x;
    int stride = gridDim.x * blockDim.x;
    for (; i < n4; i += stride) {
        float4 v = ((const float4*)s)[i];
        v.x = tf32rf(v.x); v.y = tf32rf(v.y); v.z = tf32rf(v.z); v.w = tf32rf(v.w);
        ((float4*)d)[i] = v;
    }
}

// ---------------------------------------------------------------------------
// tf32 GEMM, 3-stage cp.async pipeline, BK=32 (64 mainloop barriers).
// Block 128x256, 8 warps (64x64 each). Inputs pre-rounded -> raw-bit feed.
// ---------------------------------------------------------------------------
#define BM 128
#define BN 256
#define BK 32
#define AST 36
#define BST 264
#define ASTAGE (BM * AST)       // 4608 floats
#define BSTAGE (BK * BST)       // 8448 floats
#define GEMM_SMEM ((3 * ASTAGE + 3 * BSTAGE) * 4)   // 156672 bytes
#define NKT (DIM / BK)          // 64 k-tiles

__device__ __forceinline__ void gemm_issue(float* As, float* Bs, int kt,
                                           const float* Ag, const float* Bg, int tid) {
    const int stg = kt % 3;
    const int k0 = kt * BK;
    float* Ad = As + stg * ASTAGE;
    float* Bd = Bs + stg * BSTAGE;
#pragma unroll
    for (int i = 0; i < 4; i++) {           // A: 1024 float4
        int idx = tid + i * 256;
        int r = idx >> 3, c = (idx & 7) * 4;
        cpa16(Ad + r * AST + c, Ag + (size_t)r * DIM + k0 + c);
    }
#pragma unroll
    for (int i = 0; i < 8; i++) {           // B: 2048 float4
        int idx = tid + i * 256;
        int r = idx >> 6, c = (idx & 63) * 4;
        cpa16(Bd + r * BST + c, Bg + (size_t)(k0 + r) * DIM + c);
    }
}

// ROUND_OUT: 1 -> round outputs to tf32 grid (feeds later tensor stages)
template <int ROUND_OUT>
__device__ __forceinline__ void gemm_body(const float* Ag, const float* Bg,
                                          const float* bias, float* C,
                                          float* As, float* Bs,
                                          int bx, int by, int tid) {
    const int lane = tid & 31, wid = tid >> 5;
    const int wm = (wid & 1) * 64;
    const int wn = (wid >> 1) * 64;
    const int g = lane >> 2, t = lane & 3;

    float c[4][8][4];
#pragma unroll
    for (int mt = 0; mt < 4; mt++)
#pragma unroll
        for (int nt = 0; nt < 8; nt++)
#pragma unroll
            for (int i = 0; i < 4; i++) c[mt][nt][i] = 0.f;

    gemm_issue(As, Bs, 0, Ag, Bg, tid); CP_COMMIT();
    gemm_issue(As, Bs, 1, Ag, Bg, tid); CP_COMMIT();

    for (int kt = 0; kt < NKT; kt++) {
        CP_WAIT1();
        __syncthreads();
        if (kt + 2 < NKT) gemm_issue(As, Bs, kt + 2, Ag, Bg, tid);
        CP_COMMIT();

        const int buf = kt % 3;
        const float* Ab = As + buf * ASTAGE;
        const float* Bb = Bs + buf * BSTAGE;
#pragma unroll
        for (int kk = 0; kk < BK; kk += 8) {
            unsigned a[4][4], b[8][2];
#pragma unroll
            for (int mt = 0; mt < 4; mt++) {
                int r0 = wm + mt * 16 + g;
                a[mt][0] = __float_as_uint(Ab[r0 * AST + kk + t]);
                a[mt][1] = __float_as_uint(Ab[(r0 + 8) * AST + kk + t]);
                a[mt][2] = __float_as_uint(Ab[r0 * AST + kk + t + 4]);
                a[mt][3] = __float_as_uint(Ab[(r0 + 8) * AST + kk + t + 4]);
            }
#pragma unroll
            for (int nt = 0; nt < 8; nt++) {
                int cc = wn + nt * 8 + g;
                b[nt][0] = __float_as_uint(Bb[(kk + t) * BST + cc]);
                b[nt][1] = __float_as_uint(Bb[(kk + t + 4) * BST + cc]);
            }
#pragma unroll
            for (int mt = 0; mt < 4; mt++)
#pragma unroll
                for (int nt = 0; nt < 8; nt++)
                    mma_tf32(c[mt][nt], a[mt], b[nt]);
        }
    }

    const int rowB = by * BM + wm;
    const int colB = bx * BN + wn;
#pragma unroll
    for (int mt = 0; mt < 4; mt++) {
        int r0 = rowB + mt * 16 + g;
#pragma unroll
        for (int nt = 0; nt < 8; nt++) {
            int col = colB + nt * 8 + 2 * t;
            float b0 = bias[col], b1 = bias[col + 1];
            float2 v;
            if (ROUND_OUT) {
                v.x = tf32rf(c[mt][nt][0] + b0); v.y = tf32rf(c[mt][nt][1] + b1);
                *(float2*)(C + (size_t)r0 * DIM + col) = v;
                v.x = tf32rf(c[mt][nt][2] + b0); v.y = tf32rf(c[mt][nt][3] + b1);
                *(float2*)(C + (size_t)(r0 + 8) * DIM + col) = v;
            } else {
                v.x = c[mt][nt][0] + b0; v.y = c[mt][nt][1] + b1;
                *(float2*)(C + (size_t)r0 * DIM + col) = v;
                v.x = c[mt][nt][2] + b0; v.y = c[mt][nt][3] + b1;
                *(float2*)(C + (size_t)(r0 + 8) * DIM + col) = v;
            }
        }
    }
}

__global__ __launch_bounds__(256, 1)
void gemm_proj_kernel(const float* __restrict__ A, const float* __restrict__ W,
                      const float* __restrict__ bias, float* __restrict__ C) {
    extern __shared__ float gsm[];
    gemm_body<0>(A + (size_t)(blockIdx.y * BM) * DIM, W + blockIdx.x * BN,
                 bias, C, gsm, gsm + 3 * ASTAGE, blockIdx.x, blockIdx.y, threadIdx.x);
}

__global__ __launch_bounds__(256, 1)
void gemm_qkv_kernel(const float* __restrict__ A, const float* __restrict__ Wall,
                     const float* __restrict__ bq, const float* __restrict__ bk,
                     const float* __restrict__ bv,
                     float* __restrict__ Cq, float* __restrict__ Ck,
                     float* __restrict__ Cv) {
    extern __shared__ float gsm[];
    const float* bias; float* C;
    const float* W = Wall + (size_t)blockIdx.z * DIM * DIM;
    if (blockIdx.z == 0)      { bias = bq; C = Cq; }
    else if (blockIdx.z == 1) { bias = bk; C = Ck; }
    else                      { bias = bv; C = Cv; }
    gemm_body<1>(A + (size_t)(blockIdx.y * BM) * DIM, W + blockIdx.x * BN,
                 bias, C, gsm, gsm + 3 * ASTAGE, blockIdx.x, blockIdx.y, threadIdx.x);
}

// ---------------------------------------------------------------------------
// RMSNorm + RoPE — outputs rounded to tf32 grid
// ---------------------------------------------------------------------------
__global__ __launch_bounds__(256)
void rmsnorm_rope_kernel(const float* __restrict__ fc, const float* __restrict__ fs,
                         const float* __restrict__ gq, const float* __restrict__ gk) {
    const int s = blockIdx.x;
    const int tid = threadIdx.x;
    float* qrow = g_q + (size_t)s * DIM;
    float* krow = g_k + (size_t)s * DIM;

    float q1[4], q2[4], k1[4], k2[4];
    float sq = 0.f, sk = 0.f;
#pragma unroll
    for (int j = 0; j < 4; j++) {
        int p = tid + j * 256;
        int h = p >> 6, jj = p & 63;
        int i1 = h * DH + 2 * jj;
        float2 qv = *(const float2*)(qrow + i1);
        float2 kv = *(const float2*)(krow + i1);
        q1[j] = qv.x; q2[j] = qv.y; k1[j] = kv.x; k2[j] = kv.y;
        sq += qv.x * qv.x + qv.y * qv.y;
        sk += kv.x * kv.x + kv.y * kv.y;
    }
#pragma unroll
    for (int off = 16; off > 0; off >>= 1) {
        sq += __shfl_xor_sync(0xffffffffu, sq, off);
        sk += __shfl_xor_sync(0xffffffffu, sk, off);
    }
    __shared__ float sh[16];
    if ((tid & 31) == 0) { sh[tid >> 5] = sq; sh[8 + (tid >> 5)] = sk; }
    __syncthreads();
    float tq = 0.f, tk = 0.f;
#pragma unroll
    for (int w = 0; w < 8; w++) { tq += sh[w]; tk += sh[8 + w]; }
    const float rq = rsqrtf(tq * (1.0f / DIM) + 1e-5f);
    const float rk = rsqrtf(tk * (1.0f / DIM) + 1e-5f);

#pragma unroll
    for (int j = 0; j < 4; j++) {
        int p = tid + j * 256;
        int h = p >> 6, jj = p & 63;
        int i1 = h * DH + 2 * jj;
        float c = fc[(size_t)s * DH + 2 * jj];
        float sn = fs[(size_t)s * DH + 2 * jj + 1];
        float x1 = q1[j] * rq * gq[i1];
        float x2 = q2[j] * rq * gq[i1 + 1];
        float2 oq; oq.x = tf32rf(x1 * c - x2 * sn); oq.y = tf32rf(x1 * sn + x2 * c);
        *(float2*)(qrow + i1) = oq;
        x1 = k1[j] * rk * gk[i1];
        x2 = k2[j] * rk * gk[i1 + 1];
        float2 ok; ok.x = tf32rf(x1 * c - x2 * sn); ok.y = tf32rf(x1 * sn + x2 * c);
        *(float2*)(krow + i1) = ok;
    }
}

// ---------------------------------------------------------------------------
// Flash attention, tf32 MMA, cp.async K (double-buffered) + V (single).
// (unchanged from R6 — passing)
// ---------------------------------------------------------------------------
#define BQ 128
#define BKV 64
#define QS 132
#define KS 132
#define VS 136
#define PS 68
#define KSTG (BKV * KS)
#define ATTN_SMEM ((BQ * QS + 2 * KSTG + BKV * VS + BQ * PS) * 4)
#define NT (SEQ / BKV)

__global__ __launch_bounds__(256, 1)
void attn_kernel() {
    extern __shared__ unsigned smu[];
    unsigned* Qs = smu;
    unsigned* K0 = Qs + BQ * QS;
    unsigned* Vs = K0 + 2 * KSTG;
    unsigned* Ps = Vs + BKV * VS;

    const int h = blockIdx.y;
    const int q0 = blockIdx.x * BQ;
    const int tid = threadIdx.x;
    const int lane = tid & 31, wid = tid >> 5;
    const int g = lane >> 2, t = lane & 3;
    const int rbase = wid * 16;
    const float scale = 0.08838834764831845f;   // 1/sqrt(128)

#pragma unroll
    for (int i = 0; i < 16; i++) {
        int idx = tid + i * 256;
        int r = idx >> 5, c4 = (idx & 31) * 4;
        float4 v = *(const float4*)(g_q + (size_t)(q0 + r) * DIM + h * DH + c4);
        unsigned* dst = Qs + r * QS + c4;
        dst[0] = tf32r(v.x * scale); dst[1] = tf32r(v.y * scale);
        dst[2] = tf32r(v.z * scale); dst[3] = tf32r(v.w * scale);
    }

#pragma unroll
    for (int i = 0; i < 8; i++) {
        int idx = tid + i * 256;
        int r = idx >> 5, c4 = (idx & 31) * 4;
        cpa16(K0 + r * KS + c4, g_k + (size_t)r * DIM + h * DH + c4);
    }
    CP_COMMIT();

    float o[16][4];
#pragma unroll
    for (int nt = 0; nt < 16; nt++)
#pragma unroll
        for (int i = 0; i < 4; i++) o[nt][i] = 0.f;
    float m0 = -1e30f, m1 = -1e30f, l0 = 0.f, l1 = 0.f;

    for (int kt = 0; kt < NT; kt++) {
        if (kt == 0) CP_WAIT0();
        __syncthreads();
        const int tok0 = kt * BKV;

#pragma unroll
        for (int i = 0; i < 8; i++) {
            int idx = tid + i * 256;
            int r = idx >> 5, c4 = (idx & 31) * 4;
            cpa16(Vs + r * VS + c4, g_v + (size_t)(tok0 + r) * DIM + h * DH + c4);
        }
        CP_COMMIT();
        if (kt + 1 < NT) {
            unsigned* Kn = K0 + ((kt + 1) & 1) * KSTG;
#pragma unroll
            for (int i = 0; i < 8; i++) {
                int idx = tid + i * 256;
                int r = idx >> 5, c4 = (idx & 31) * 4;
                cpa16(Kn + r * KS + c4, g_k + (size_t)(tok0 + BKV + r) * DIM + h * DH + c4);
            }
            CP_COMMIT();
        }

        const unsigned* Kb = K0 + (kt & 1) * KSTG;

        float s[8][4];
#pragma unroll
        for (int nt = 0; nt < 8; nt++)
#pragma unroll
            for (int i = 0; i < 4; i++) s[nt][i] = 0.f;

#pragma unroll
        for (int kk = 0; kk < DH; kk += 8) {
            unsigned a[4];
            a[0] = Qs[(rbase + g) * QS + kk + t];
            a[1] = Qs[(rbase + g + 8) * QS + kk + t];
            a[2] = Qs[(rbase + g) * QS + kk + t + 4];
            a[3] = Qs[(rbase + g + 8) * QS + kk + t + 4];
#pragma unroll
            for (int nt = 0; nt < 8; nt++) {
                unsigned b[2];
                b[0] = Kb[(nt * 8 + g) * KS + kk + t];
                b[1] = Kb[(nt * 8 + g) * KS + kk + t + 4];
                mma_tf32(s[nt], a, b);
            }
        }

        float mx0 = -1e30f, mx1 = -1e30f;
#pragma unroll
        for (int nt = 0; nt < 8; nt++) {
            mx0 = fmaxf(mx0, fmaxf(s[nt][0], s[nt][1]));
            mx1 = fmaxf(mx1, fmaxf(s[nt][2], s[nt][3]));
        }
        mx0 = fmaxf(mx0, __shfl_xor_sync(0xffffffffu, mx0, 1));
        mx0 = fmaxf(mx0, __shfl_xor_sync(0xffffffffu, mx0, 2));
        mx1 = fmaxf(mx1, __shfl_xor_sync(0xffffffffu, mx1, 1));
        mx1 = fmaxf(mx1, __shfl_xor_sync(0xffffffffu, mx1, 2));

        float mn0 = fmaxf(m0, mx0), mn1 = fmaxf(m1, mx1);
        float al0 = __expf(m0 - mn0), al1 = __expf(m1 - mn1);
        float sum0 = 0.f, sum1 = 0.f;
#pragma unroll
        for (int nt = 0; nt < 8; nt++) {
            float p00 = __expf(s[nt][0] - mn0);
            float p01 = __expf(s[nt][1] - mn0);
            float p10 = __expf(s[nt][2] - mn1);
            float p11 = __expf(s[nt][3] - mn1);
            sum0 += p00 + p01; sum1 += p10 + p11;
            uint2 u0; u0.x = tf32r(p00); u0.y = tf32r(p01);
            *(uint2*)&Ps[(rbase + g) * PS + nt * 8 + 2 * t] = u0;
            uint2 u1; u1.x = tf32r(p10); u1.y = tf32r(p11);
            *(uint2*)&Ps[(rbase + g + 8) * PS + nt * 8 + 2 * t] = u1;
        }
        sum0 += __shfl_xor_sync(0xffffffffu, sum0, 1);
        sum0 += __shfl_xor_sync(0xffffffffu, sum0, 2);
        sum1 += __shfl_xor_sync(0xffffffffu, sum1, 1);
        sum1 += __shfl_xor_sync(0xffffffffu, sum1, 2);
        l0 = l0 * al0 + sum0; l1 = l1 * al1 + sum1;
        m0 = mn0; m1 = mn1;
#pragma unroll
        for (int nt = 0; nt < 16; nt++) {
            o[nt][0] *= al0; o[nt][1] *= al0;
            o[nt][2] *= al1; o[nt][3] *= al1;
        }

        CP_WAIT0();
        __syncthreads();

#pragma unroll
        for (int kk = 0; kk < BKV; kk += 8) {
            unsigned a[4];
            a[0] = Ps[(rbase + g) * PS + kk + t];
            a[1] = Ps[(rbase + g + 8) * PS + kk + t];
            a[2] = Ps[(rbase + g) * PS + kk + t + 4];
            a[3] = Ps[(rbase + g + 8) * PS + kk + t + 4];
#pragma unroll
            for (int nt = 0; nt < 16; nt++) {
                unsigned b[2];
                b[0] = Vs[(kk + t) * VS + nt * 8 + g];
                b[1] = Vs[(kk + t + 4) * VS + nt * 8 + g];
                mma_tf32(o[nt], a, b);
            }
        }
    }

    const float inv0 = 1.0f / l0, inv1 = 1.0f / l1;
    const int r0 = q0 + rbase + g, r1 = r0 + 8;
#pragma unroll
    for (int nt = 0; nt < 16; nt++) {
        int col = h * DH + nt * 8 + 2 * t;
        float2 w0; w0.x = tf32rf(o[nt][0] * inv0); w0.y = tf32rf(o[nt][1] * inv0);
        *(float2*)(g_att + (size_t)r0 * DIM + col) = w0;
        float2 w1; w1.x = tf32rf(o[nt][2] * inv1); w1.y = tf32rf(o[nt][3] * inv1);
        *(float2*)(g_att + (size_t)r1 * DIM + col) = w1;
    }
}

// ---------------------------------------------------------------------------
// Host launch
// ---------------------------------------------------------------------------
extern "C" void kernel_launch(void* const* d_in, const int* in_sizes, int n_in,
                              void* d_out, int out_size) {
    const float* x  = (const float*)d_in[0];
    const float* fc = (const float*)d_in[1];
    const float* fs = (const float*)d_in[2];
    const float* Wq = (const float*)d_in[3];
    const float* bq = (const float*)d_in[4];
    const float* Wk = (const float*)d_in[5];
    const float* bk = (const float*)d_in[6];
    const float* Wv = (const float*)d_in[7];
    const float* bv = (const float*)d_in[8];
    const float* Wo = (const float*)d_in[9];
    const float* bo = (const float*)d_in[10];
    const float* gq = (const float*)d_in[11];
    const float* gk = (const float*)d_in[12];
    float* out = (float*)d_out;

    float *q, *k, *v, *att, *xt, *w;
    cudaGetSymbolAddress((void**)&q,   g_q);
    cudaGetSymbolAddress((void**)&k,   g_k);
    cudaGetSymbolAddress((void**)&v,   g_v);
    cudaGetSymbolAddress((void**)&att, g_att);
    cudaGetSymbolAddress((void**)&xt,  g_xt);
    cudaGetSymbolAddress((void**)&w,   g_w);

    cudaFuncSetAttribute(gemm_qkv_kernel, cudaFuncAttributeMaxDynamicSharedMemorySize,
                         GEMM_SMEM);
    cudaFuncSetAttribute(gemm_proj_kernel, cudaFuncAttributeMaxDynamicSharedMemorySize,
                         GEMM_SMEM);
    cudaFuncSetAttribute(attn_kernel, cudaFuncAttributeMaxDynamicSharedMemorySize,
                         ATTN_SMEM);

    roundcvt5_kernel<<<dim3(160, 1, 5), 256>>>(x, Wq, Wk, Wv, Wo);

    dim3 qkv_grid(DIM / BN, SEQ / BM, 3);
    gemm_qkv_kernel<<<qkv_grid, 256, GEMM_SMEM>>>(xt, w, bq, bk, bv, q, k, v);
    rmsnorm_rope_kernel<<<SEQ, 256>>>(fc, fs, gq, gk);
    attn_kernel<<<dim3(SEQ / BQ, NH), 256, ATTN_SMEM>>>();
    dim3 gemm_grid(DIM / BN, SEQ / BM);
    gemm_proj_kernel<<<gemm_grid, 256, GEMM_SMEM>>>(att, w + (size_t)3 * DIM * DIM,
                                                    bo, out);
}

// round 8
// speedup vs baseline: 8.8674x; 1.8279x over previous
#include <cuda_runtime.h>
#include <cuda_fp16.h>
#include <math.h>

#define SEQ 4096
#define DIM 2048
#define NH 16
#define DH 128
#define D2 (DIM / 2)            // u32 (half2) per row

// Scratch (static device arrays — no allocations allowed)
__device__ float    g_q[SEQ * DIM];      // Q proj (fp32, pre-norm)
__device__ float    g_k[SEQ * DIM];      // K proj (fp32, pre-norm)
__device__ unsigned g_xh[SEQ * D2];      // x half-packed [row][k2]
__device__ unsigned g_qh[SEQ * D2];      // q half-packed, scaled (post norm+rope)
__device__ unsigned g_kh[SEQ * D2];      // k half-packed (post norm+rope)
__device__ __half   g_vt[(size_t)DIM * SEQ];   // V transposed [dimcol][token]
__device__ unsigned g_ath[SEQ * D2];     // attention out half-packed [row][k2]
__device__ unsigned g_wp[(size_t)4 * DIM * D2];  // W^T half-packed [mat][n][k2]

__device__ __forceinline__ unsigned h2u(__half2 h) { return *(unsigned*)&h; }

__device__ __forceinline__ void mma_f16(float* c, const unsigned* a, const unsigned* b) {
    asm volatile(
        "mma.sync.aligned.m16n8k16.row.col.f32.f16.f16.f32 "
        "{%0,%1,%2,%3}, {%4,%5,%6,%7}, {%8,%9}, {%0,%1,%2,%3};\n"
        : "+f"(c[0]), "+f"(c[1]), "+f"(c[2]), "+f"(c[3])
        : "r"(a[0]), "r"(a[1]), "r"(a[2]), "r"(a[3]), "r"(b[0]), "r"(b[1]));
}

__device__ __forceinline__ void cpa16(void* dst, const void* src) {
    unsigned d = (unsigned)__cvta_generic_to_shared(dst);
    asm volatile("cp.async.cg.shared.global [%0], [%1], 16;\n" :: "r"(d), "l"(src));
}
#define CP_COMMIT() asm volatile("cp.async.commit_group;\n" ::: "memory")
#define CP_WAIT1()  asm volatile("cp.async.wait_group 1;\n" ::: "memory")
#define CP_WAIT0()  asm volatile("cp.async.wait_group 0;\n" ::: "memory")

// ---------------------------------------------------------------------------
// Producers: pack x (row-major k-pairs) and W (transposed, k-pairs per column)
// ---------------------------------------------------------------------------
__global__ void pack_x_kernel(const float* __restrict__ x) {
    int i = blockIdx.x * blockDim.x + threadIdx.x;
    int stride = gridDim.x * blockDim.x;
    for (; i < SEQ * D2; i += stride) {
        float2 v = ((const float2*)x)[i];
        g_xh[i] = h2u(__floats2half2_rn(v.x, v.y));
    }
}

__global__ void packw_kernel(const float* __restrict__ Wq, const float* __restrict__ Wk,
                             const float* __restrict__ Wv, const float* __restrict__ Wo) {
    __shared__ float sm[32][33];
    const float* W;
    if (blockIdx.z == 0)      W = Wq;
    else if (blockIdx.z == 1) W = Wk;
    else if (blockIdx.z == 2) W = Wv;
    else                      W = Wo;
    unsigned* out = g_wp + (size_t)blockIdx.z * DIM * D2;
    const int k0 = blockIdx.x * 32, n0 = blockIdx.y * 32;
    const int tx = threadIdx.x & 31, ty = threadIdx.x >> 5;   // 32 x 8
#pragma unroll
    for (int i = 0; i < 4; i++)
        sm[ty + i * 8][tx] = W[(size_t)(k0 + ty + i * 8) * DIM + n0 + tx];
    __syncthreads();
    int idx = threadIdx.x;
#pragma unroll
    for (int p = 0; p < 2; p++, idx += 256) {
        int nl = idx >> 4, c = idx & 15;
        out[(size_t)(n0 + nl) * D2 + (k0 >> 1) + c] =
            h2u(__floats2half2_rn(sm[2 * c][nl], sm[2 * c + 1][nl]));
    }
}

// ---------------------------------------------------------------------------
// fp16 GEMM: BM=128, BN=256, BK=64, 3-stage cp.async, 8 warps (64x64 each).
// A: [row][k2] packed; B: [n][k2] packed (W^T). fp32 accumulate.
// ---------------------------------------------------------------------------
#define BM 128
#define BN 256
#define BK2 32                   // u32 per k-tile (64 halves)
#define AST 36
#define BST 36
#define ASTG (BM * AST)          // 4608 u32
#define BSTG (BN * BST)          // 9216 u32
#define GEMM_SMEM (3 * (ASTG + BSTG) * 4)    // 165888 B
#define NKT (D2 / BK2)           // 32

__device__ __forceinline__ void gemm_issue(unsigned* As, unsigned* Bs, int kt,
                                           const unsigned* Ag, const unsigned* Bg, int tid) {
    const int stg = kt % 3;
    const int k2 = kt * BK2;
    unsigned* Ad = As + stg * ASTG;
    unsigned* Bd = Bs + stg * BSTG;
#pragma unroll
    for (int i = 0; i < 4; i++) {            // A: 128 rows x 8 cp16
        int idx = tid + i * 256;
        int r = idx >> 3, c = (idx & 7) * 4;
        cpa16(Ad + r * AST + c, Ag + (size_t)r * D2 + k2 + c);
    }
#pragma unroll
    for (int i = 0; i < 8; i++) {            // B: 256 rows x 8 cp16
        int idx = tid + i * 256;
        int r = idx >> 3, c = (idx & 7) * 4;
        cpa16(Bd + r * BST + c, Bg + (size_t)r * D2 + k2 + c);
    }
}

__device__ __forceinline__ void gemm_mainloop(const unsigned* Ag, const unsigned* Bg,
                                              unsigned* As, unsigned* Bs,
                                              float c[4][8][4], int tid) {
    const int lane = tid & 31, wid = tid >> 5;
    const int wm = (wid & 1) * 64;
    const int wn = (wid >> 1) * 64;
    const int g = lane >> 2, t = lane & 3;

#pragma unroll
    for (int mt = 0; mt < 4; mt++)
#pragma unroll
        for (int nt = 0; nt < 8; nt++)
#pragma unroll
            for (int i = 0; i < 4; i++) c[mt][nt][i] = 0.f;

    gemm_issue(As, Bs, 0, Ag, Bg, tid); CP_COMMIT();
    gemm_issue(As, Bs, 1, Ag, Bg, tid); CP_COMMIT();

    for (int kt = 0; kt < NKT; kt++) {
        CP_WAIT1();
        __syncthreads();
        if (kt + 2 < NKT) gemm_issue(As, Bs, kt + 2, Ag, Bg, tid);
        CP_COMMIT();

        const int buf = kt % 3;
        const unsigned* Ab = As + buf * ASTG;
        const unsigned* Bb = Bs + buf * BSTG;
#pragma unroll
        for (int kk2 = 0; kk2 < BK2; kk2 += 8) {
            unsigned a[4][4], b[8][2];
#pragma unroll
            for (int mt = 0; mt < 4; mt++) {
                int r0 = wm + mt * 16 + g;
                a[mt][0] = Ab[r0 * AST + kk2 + t];
                a[mt][1] = Ab[(r0 + 8) * AST + kk2 + t];
                a[mt][2] = Ab[r0 * AST + kk2 + t + 4];
                a[mt][3] = Ab[(r0 + 8) * AST + kk2 + t + 4];
            }
#pragma unroll
            for (int nt = 0; nt < 8; nt++) {
                int cc = wn + nt * 8 + g;
                b[nt][0] = Bb[cc * BST + kk2 + t];
                b[nt][1] = Bb[cc * BST + kk2 + t + 4];
            }
#pragma unroll
            for (int mt = 0; mt < 4; mt++)
#pragma unroll
                for (int nt = 0; nt < 8; nt++)
                    mma_f16(c[mt][nt], a[mt], b[nt]);
        }
    }
}

// QKV: z=0 -> Q fp32, z=1 -> K fp32, z=2 -> V half transposed (g_vt)
__global__ __launch_bounds__(256, 1)
void gemm_qkv_kernel(const float* __restrict__ bq, const float* __restrict__ bk,
                     const float* __restrict__ bv) {
    extern __shared__ unsigned gsm[];
    const int tid = threadIdx.x;
    const int lane = tid & 31, wid = tid >> 5;
    const int wm = (wid & 1) * 64, wn = (wid >> 1) * 64;
    const int g = lane >> 2, t = lane & 3;
    const int z = blockIdx.z;

    const unsigned* Ag = g_xh + (size_t)(blockIdx.y * BM) * D2;
    const unsigned* Bg = g_wp + (size_t)z * DIM * D2 + (size_t)(blockIdx.x * BN) * D2;

    float c[4][8][4];
    gemm_mainloop(Ag, Bg, gsm, gsm + 3 * ASTG, c, tid);

    const int rowB = blockIdx.y * BM + wm;
    const int colB = blockIdx.x * BN + wn;
    const float* bias = (z == 0) ? bq : (z == 1) ? bk : bv;

    if (z < 2) {
        float* C = (z == 0) ? g_q : g_k;
#pragma unroll
        for (int mt = 0; mt < 4; mt++) {
            int r0 = rowB + mt * 16 + g;
#pragma unroll
            for (int nt = 0; nt < 8; nt++) {
                int col = colB + nt * 8 + 2 * t;
                float b0 = bias[col], b1 = bias[col + 1];
                float2 v;
                v.x = c[mt][nt][0] + b0; v.y = c[mt][nt][1] + b1;
                *(float2*)(C + (size_t)r0 * DIM + col) = v;
                v.x = c[mt][nt][2] + b0; v.y = c[mt][nt][3] + b1;
                *(float2*)(C + (size_t)(r0 + 8) * DIM + col) = v;
            }
        }
    } else {
        // V: write transposed half g_vt[col][token]
#pragma unroll
        for (int mt = 0; mt < 4; mt++) {
            int r0 = rowB + mt * 16 + g;
#pragma unroll
            for (int nt = 0; nt < 8; nt++) {
                int col = colB + nt * 8 + 2 * t;
                float b0 = bias[col], b1 = bias[col + 1];
                g_vt[(size_t)col * SEQ + r0]           = __float2half(c[mt][nt][0] + b0);
                g_vt[(size_t)(col + 1) * SEQ + r0]     = __float2half(c[mt][nt][1] + b1);
                g_vt[(size_t)col * SEQ + r0 + 8]       = __float2half(c[mt][nt][2] + b0);
                g_vt[(size_t)(col + 1) * SEQ + r0 + 8] = __float2half(c[mt][nt][3] + b1);
            }
        }
    }
}

// Output projection: A = g_ath, B = Wo^T packed, out fp32 + bias
__global__ __launch_bounds__(256, 1)
void gemm_proj_kernel(const float* __restrict__ bias, float* __restrict__ C) {
    extern __shared__ unsigned gsm[];
    const int tid = threadIdx.x;
    const int lane = tid & 31, wid = tid >> 5;
    const int wm = (wid & 1) * 64, wn = (wid >> 1) * 64;
    const int g = lane >> 2, t = lane & 3;

    const unsigned* Ag = g_ath + (size_t)(blockIdx.y * BM) * D2;
    const unsigned* Bg = g_wp + (size_t)3 * DIM * D2 + (size_t)(blockIdx.x * BN) * D2;

    float c[4][8][4];
    gemm_mainloop(Ag, Bg, gsm, gsm + 3 * ASTG, c, tid);

    const int rowB = blockIdx.y * BM + wm;
    const int colB = blockIdx.x * BN + wn;
#pragma unroll
    for (int mt = 0; mt < 4; mt++) {
        int r0 = rowB + mt * 16 + g;
#pragma unroll
        for (int nt = 0; nt < 8; nt++) {
            int col = colB + nt * 8 + 2 * t;
            float b0 = bias[col], b1 = bias[col + 1];
            float2 v;
            v.x = c[mt][nt][0] + b0; v.y = c[mt][nt][1] + b1;
            *(float2*)(C + (size_t)r0 * DIM + col) = v;
            v.x = c[mt][nt][2] + b0; v.y = c[mt][nt][3] + b1;
            *(float2*)(C + (size_t)(r0 + 8) * DIM + col) = v;
        }
    }
}

// ---------------------------------------------------------------------------
// RMSNorm + RoPE: reads fp32 g_q/g_k, writes half-packed g_qh (scaled) / g_kh
// ---------------------------------------------------------------------------
__global__ __launch_bounds__(256)
void rmsnorm_rope_kernel(const float* __restrict__ fc, const float* __restrict__ fs,
                         const float* __restrict__ gq, const float* __restrict__ gk) {
    const int s = blockIdx.x;
    const int tid = threadIdx.x;
    const float* qrow = g_q + (size_t)s * DIM;
    const float* krow = g_k + (size_t)s * DIM;
    const float qscale = 0.08838834764831845f;   // 1/sqrt(128)

    float q1[4], q2[4], k1[4], k2[4];
    float sq = 0.f, sk = 0.f;
#pragma unroll
    for (int j = 0; j < 4; j++) {
        int p = tid + j * 256;
        int h = p >> 6, jj = p & 63;
        int i1 = h * DH + 2 * jj;
        float2 qv = *(const float2*)(qrow + i1);
        float2 kv = *(const float2*)(krow + i1);
        q1[j] = qv.x; q2[j] = qv.y; k1[j] = kv.x; k2[j] = kv.y;
        sq += qv.x * qv.x + qv.y * qv.y;
        sk += kv.x * kv.x + kv.y * kv.y;
    }
#pragma unroll
    for (int off = 16; off > 0; off >>= 1) {
        sq += __shfl_xor_sync(0xffffffffu, sq, off);
        sk += __shfl_xor_sync(0xffffffffu, sk, off);
    }
    __shared__ float sh[16];
    if ((tid & 31) == 0) { sh[tid >> 5] = sq; sh[8 + (tid >> 5)] = sk; }
    __syncthreads();
    float tq = 0.f, tk = 0.f;
#pragma unroll
    for (int w = 0; w < 8; w++) { tq += sh[w]; tk += sh[8 + w]; }
    const float rq = rsqrtf(tq * (1.0f / DIM) + 1e-5f);
    const float rk = rsqrtf(tk * (1.0f / DIM) + 1e-5f);

#pragma unroll
    for (int j = 0; j < 4; j++) {
        int p = tid + j * 256;
        int h = p >> 6, jj = p & 63;
        int i1 = h * DH + 2 * jj;
        float c = fc[(size_t)s * DH + 2 * jj];
        float sn = fs[(size_t)s * DH + 2 * jj + 1];
        float x1 = q1[j] * rq * gq[i1];
        float x2 = q2[j] * rq * gq[i1 + 1];
        g_qh[(size_t)s * D2 + (i1 >> 1)] =
            h2u(__floats2half2_rn((x1 * c - x2 * sn) * qscale,
                                  (x1 * sn + x2 * c) * qscale));
        x1 = k1[j] * rk * gk[i1];
        x2 = k2[j] * rk * gk[i1 + 1];
        g_kh[(size_t)s * D2 + (i1 >> 1)] =
            h2u(__floats2half2_rn(x1 * c - x2 * sn, x1 * sn + x2 * c));
    }
}

// ---------------------------------------------------------------------------
// Flash attention, fp16 m16n8k16. BQ=128, BKV=64, 8 warps.
// Q fragments in registers; K double-buffered cp.async; V via g_vt (token-pairs).
// ---------------------------------------------------------------------------
#define BQ 128
#define BKV 64
#define KS2 68
#define VS2 36
#define PS2 36
#define KSTG2 (BKV * KS2)         // 4352 u32
#define ATTN_SMEM ((2 * KSTG2 + DH * VS2 + BQ * PS2) * 4)   // 71680 B
#define NT (SEQ / BKV)            // 64

__global__ __launch_bounds__(256)
void attn_kernel() {
    extern __shared__ unsigned smu[];
    unsigned* K0 = smu;
    unsigned* Vs = K0 + 2 * KSTG2;
    unsigned* Ps = Vs + DH * VS2;

    const int h = blockIdx.y;
    const int q0 = blockIdx.x * BQ;
    const int tid = threadIdx.x;
    const int lane = tid & 31, wid = tid >> 5;
    const int g = lane >> 2, t = lane & 3;
    const int rbase = wid * 16;
    const unsigned* vt32 = (const unsigned*)g_vt;

    // K(0) -> buf0
#pragma unroll
    for (int i = 0; i < 4; i++) {
        int idx = tid + i * 256;
        int r = idx >> 4, c = (idx & 15) * 4;
        cpa16(K0 + r * KS2 + c, g_kh + (size_t)r * D2 + h * 64 + c);
    }
    CP_COMMIT();

    // Q fragments -> registers (reused every tile)
    unsigned qf[8][4];
    {
        const unsigned* qr0 = g_qh + (size_t)(q0 + rbase + g) * D2 + h * 64;
        const unsigned* qr1 = qr0 + 8 * D2;
#pragma unroll
        for (int ks = 0; ks < 8; ks++) {
            int kk2 = ks * 8;
            qf[ks][0] = qr0[kk2 + t];
            qf[ks][1] = qr1[kk2 + t];
            qf[ks][2] = qr0[kk2 + t + 4];
            qf[ks][3] = qr1[kk2 + t + 4];
        }
    }

    float o[16][4];
#pragma unroll
    for (int nt = 0; nt < 16; nt++)
#pragma unroll
        for (int i = 0; i < 4; i++) o[nt][i] = 0.f;
    float m0 = -1e30f, m1 = -1e30f, l0 = 0.f, l1 = 0.f;

    for (int kt = 0; kt < NT; kt++) {
        if (kt == 0) CP_WAIT0();
        __syncthreads();                  // K(kt) visible; prior PV done
        const int tok0 = kt * BKV;

        // issue V(kt): g_vt rows = dim-col, 64 tokens (32 u32)
#pragma unroll
        for (int i = 0; i < 4; i++) {
            int idx = tid + i * 256;
            int r = idx >> 3, c = (idx & 7) * 4;
            cpa16(Vs + r * VS2 + c,
                  vt32 + (size_t)(h * DH + r) * (SEQ / 2) + (tok0 >> 1) + c);
        }
        CP_COMMIT();
        if (kt + 1 < NT) {
            unsigned* Kn = K0 + ((kt + 1) & 1) * KSTG2;
#pragma unroll
            for (int i = 0; i < 4; i++) {
                int idx = tid + i * 256;
                int r = idx >> 4, c = (idx & 15) * 4;
                cpa16(Kn + r * KS2 + c,
                      g_kh + (size_t)(tok0 + BKV + r) * D2 + h * 64 + c);
            }
            CP_COMMIT();
        }

        const unsigned* Kb = K0 + (kt & 1) * KSTG2;

        // ---- S = Q K^T ----
        float s[8][4];
#pragma unroll
        for (int nt = 0; nt < 8; nt++)
#pragma unroll
            for (int i = 0; i < 4; i++) s[nt][i] = 0.f;

#pragma unroll
        for (int ks = 0; ks < 8; ks++) {
            int kk2 = ks * 8;
#pragma unroll
            for (int nt = 0; nt < 8; nt++) {
                unsigned b[2];
                b[0] = Kb[(nt * 8 + g) * KS2 + kk2 + t];
                b[1] = Kb[(nt * 8 + g) * KS2 + kk2 + t + 4];
                mma_f16(s[nt], qf[ks], b);
            }
        }

        // ---- online softmax ----
        float mx0 = -1e30f, mx1 = -1e30f;
#pragma unroll
        for (int nt = 0; nt < 8; nt++) {
            mx0 = fmaxf(mx0, fmaxf(s[nt][0], s[nt][1]));
            mx1 = fmaxf(mx1, fmaxf(s[nt][2], s[nt][3]));
        }
        mx0 = fmaxf(mx0, __shfl_xor_sync(0xffffffffu, mx0, 1));
        mx0 = fmaxf(mx0, __shfl_xor_sync(0xffffffffu, mx0, 2));
        mx1 = fmaxf(mx1, __shfl_xor_sync(0xffffffffu, mx1, 1));
        mx1 = fmaxf(mx1, __shfl_xor_sync(0xffffffffu, mx1, 2));

        float mn0 = fmaxf(m0, mx0), mn1 = fmaxf(m1, mx1);
        float al0 = __expf(m0 - mn0), al1 = __expf(m1 - mn1);
        float sum0 = 0.f, sum1 = 0.f;
#pragma unroll
        for (int nt = 0; nt < 8; nt++) {
            float p00 = __expf(s[nt][0] - mn0);
            float p01 = __expf(s[nt][1] - mn0);
            float p10 = __expf(s[nt][2] - mn1);
            float p11 = __expf(s[nt][3] - mn1);
            sum0 += p00 + p01; sum1 += p10 + p11;
            Ps[(rbase + g) * PS2 + nt * 4 + t]     = h2u(__floats2half2_rn(p00, p01));
            Ps[(rbase + g + 8) * PS2 + nt * 4 + t] = h2u(__floats2half2_rn(p10, p11));
        }
        sum0 += __shfl_xor_sync(0xffffffffu, sum0, 1);
        sum0 += __shfl_xor_sync(0xffffffffu, sum0, 2);
        sum1 += __shfl_xor_sync(0xffffffffu, sum1, 1);
        sum1 += __shfl_xor_sync(0xffffffffu, sum1, 2);
        l0 = l0 * al0 + sum0; l1 = l1 * al1 + sum1;
        m0 = mn0; m1 = mn1;
#pragma unroll
        for (int nt = 0; nt < 16; nt++) {
            o[nt][0] *= al0; o[nt][1] *= al0;
            o[nt][2] *= al1; o[nt][3] *= al1;
        }

        CP_WAIT0();          // V(kt) (+K(kt+1)) landed
        __syncthreads();     // V + P visible

        // ---- O += P V ----
#pragma unroll
        for (int ks = 0; ks < 4; ks++) {
            int kk2 = ks * 8;
            unsigned a[4];
            a[0] = Ps[(rbase + g) * PS2 + kk2 + t];
            a[1] = Ps[(rbase + g + 8) * PS2 + kk2 + t];
            a[2] = Ps[(rbase + g) * PS2 + kk2 + t + 4];
            a[3] = Ps[(rbase + g + 8) * PS2 + kk2 + t + 4];
#pragma unroll
            for (int nt = 0; nt < 16; nt++) {
                unsigned b[2];
                b[0] = Vs[(nt * 8 + g) * VS2 + kk2 + t];
                b[1] = Vs[(nt * 8 + g) * VS2 + kk2 + t + 4];
                mma_f16(o[nt], a, b);
            }
        }
    }

    // epilogue -> half-packed g_ath
    const float inv0 = 1.0f / l0, inv1 = 1.0f / l1;
    const int r0 = q0 + rbase + g, r1 = r0 + 8;
#pragma unroll
    for (int nt = 0; nt < 16; nt++) {
        int c2 = h * 64 + nt * 4 + t;
        g_ath[(size_t)r0 * D2 + c2] =
            h2u(__floats2half2_rn(o[nt][0] * inv0, o[nt][1] * inv0));
        g_ath[(size_t)r1 * D2 + c2] =
            h2u(__floats2half2_rn(o[nt][2] * inv1, o[nt][3] * inv1));
    }
}

// ---------------------------------------------------------------------------
// Host launch
// ---------------------------------------------------------------------------
extern "C" void kernel_launch(void* const* d_in, const int* in_sizes, int n_in,
                              void* d_out, int out_size) {
    const float* x  = (const float*)d_in[0];
    const float* fc = (const float*)d_in[1];
    const float* fs = (const float*)d_in[2];
    const float* Wq = (const float*)d_in[3];
    const float* bq = (const float*)d_in[4];
    const float* Wk = (const float*)d_in[5];
    const float* bk = (const float*)d_in[6];
    const float* Wv = (const float*)d_in[7];
    const float* bv = (const float*)d_in[8];
    const float* Wo = (const float*)d_in[9];
    const float* bo = (const float*)d_in[10];
    const float* gq = (const float*)d_in[11];
    const float* gk = (const float*)d_in[12];
    float* out = (float*)d_out;

    cudaFuncSetAttribute(gemm_qkv_kernel, cudaFuncAttributeMaxDynamicSharedMemorySize,
                         GEMM_SMEM);
    cudaFuncSetAttribute(gemm_proj_kernel, cudaFuncAttributeMaxDynamicSharedMemorySize,
                         GEMM_SMEM);
    cudaFuncSetAttribute(attn_kernel, cudaFuncAttributeMaxDynamicSharedMemorySize,
                         ATTN_SMEM);

    pack_x_kernel<<<1024, 256>>>(x);
    packw_kernel<<<dim3(DIM / 32, DIM / 32, 4), 256>>>(Wq, Wk, Wv, Wo);

    gemm_qkv_kernel<<<dim3(DIM / BN, SEQ / BM, 3), 256, GEMM_SMEM>>>(bq, bk, bv);
    rmsnorm_rope_kernel<<<SEQ, 256>>>(fc, fs, gq, gk);
    attn_kernel<<<dim3(SEQ / BQ, NH), 256, ATTN_SMEM>>>();
    gemm_proj_kernel<<<dim3(DIM / BN, SEQ / BM), 256, GEMM_SMEM>>>(bo, out);
}